// round 12
// baseline (speedup 1.0000x reference)
#include <cuda_runtime.h>

#define Tt   12
#define Nn   100000
#define CINc 16
#define Ee   20000
#define NNZn 160000
#define Hh   64
#define Pp   12

#define TN   (Tt * Nn)
#define TE   (Tt * Ee)
#define TNNZ (Tt * NNZn)

typedef unsigned long long u64;

// ---- f32x2 packed helpers ----
__device__ __forceinline__ u64 pk2(float lo, float hi) {
    u64 r;
    asm("mov.b64 %0, {%1, %2};" : "=l"(r) : "f"(lo), "f"(hi));
    return r;
}
__device__ __forceinline__ void upk2(float& lo, float& hi, u64 v) {
    asm("mov.b64 {%0, %1}, %2;" : "=f"(lo), "=f"(hi) : "l"(v));
}
__device__ __forceinline__ u64 fma2(u64 a, u64 b, u64 c) {
    u64 d;
    asm("fma.rn.f32x2 %0, %1, %2, %3;" : "=l"(d) : "l"(a), "l"(b), "l"(c));
    return d;
}
// ---- tf32 helpers ----
__device__ __forceinline__ unsigned f2tf(float f) {
    unsigned r;
    asm("cvt.rna.tf32.f32 %0, %1;" : "=r"(r) : "f"(f));
    return r;
}
__device__ __forceinline__ void mma_tf32(float& c0, float& c1, float& c2, float& c3,
                                         unsigned a0, unsigned a1, unsigned a2, unsigned a3,
                                         unsigned b0, unsigned b1) {
    asm volatile(
        "mma.sync.aligned.m16n8k8.row.col.f32.tf32.tf32.f32 "
        "{%0,%1,%2,%3}, {%4,%5,%6,%7}, {%8,%9}, {%0,%1,%2,%3};"
        : "+f"(c0), "+f"(c1), "+f"(c2), "+f"(c3)
        : "r"(a0), "r"(a1), "r"(a2), "r"(a3), "r"(b0), "r"(b1));
}

// ---------------- scratch ----------------
__device__ float g_xd[(size_t)TN * CINc];
__device__ float g_es[(size_t)TE * Hh];
__device__ float g_edge1[(size_t)TE * Hh];
__device__ float g_agg[(size_t)Hh * Nn * 9];
__device__ float g_eagg[(size_t)Hh * Ee * 9];
__device__ float g_dinv[TN];
__device__ float g_binv[TE];
__device__ float g_wnat2[192 * 64];
__device__ float g_weat2[192 * 64];
__device__ uint4 g_wm1tf4[576 * 64 / 4];

__device__ int g_degN[TN];
__device__ int g_degE[TE];
__device__ int g_offN[TN + 1];
__device__ int g_offE[TE + 1];
__device__ int g_curN[TN];
__device__ int g_curE[TE];
__device__ int g_nlist[TNNZ];
__device__ int g_elist[TNNZ];
__device__ int g_part[1024];

// ---------------- zero ----------------
__global__ void k_zero() {
    int i = blockIdx.x * blockDim.x + threadIdx.x;
    int stride = gridDim.x * blockDim.x;
    for (int j = i; j < TN; j += stride) { g_degN[j] = 0; g_curN[j] = 0; }
    for (int j = i; j < TE; j += stride) { g_degE[j] = 0; g_curE[j] = 0; }
}

__global__ void k_count(const int* __restrict__ ni, const int* __restrict__ ei) {
    int i = blockIdx.x * blockDim.x + threadIdx.x;
    if (i >= TNNZ) return;
    int t = i / NNZn;
    atomicAdd(&g_degN[t * Nn + ni[i]], 1);
    atomicAdd(&g_degE[t * Ee + ei[i]], 1);
}

__global__ void k_inv() {
    int i = blockIdx.x * blockDim.x + threadIdx.x;
    if (i < TN) { int d = g_degN[i]; g_dinv[i] = d > 0 ? rsqrtf((float)d) : 0.f; }
    if (i < TE) { int c = g_degE[i]; g_binv[i] = c > 0 ? 1.f / (float)c : 0.f; }
}

// ---------------- xd = x * dinv ----------------
__global__ void k_xd(const float* __restrict__ nf) {
    int gi = blockIdx.x * blockDim.x + threadIdx.x;
    if (gi >= TN * 4) return;
    int u = gi >> 2, q = gi & 3;
    float d = g_dinv[u];
    float4 v = ((const float4*)nf)[(size_t)u * 4 + q];
    v.x *= d; v.y *= d; v.z *= d; v.w *= d;
    ((float4*)g_xd)[(size_t)u * 4 + q] = v;
}

// ---------------- scans ----------------
template <int SEL>
__global__ void k_scanA() {
    const int* cnt = SEL ? g_degN : g_degE;
    const int n = SEL ? TN : TE;
    __shared__ int sh[256];
    int b = blockIdx.x, t = threadIdx.x;
    int i0 = b * 4096 + t * 16;
    int s = 0;
#pragma unroll
    for (int k = 0; k < 16; k++) { int i = i0 + k; if (i < n) s += cnt[i]; }
    sh[t] = s; __syncthreads();
    for (int off = 128; off; off >>= 1) {
        if (t < off) sh[t] += sh[t + off];
        __syncthreads();
    }
    if (t == 0) g_part[b] = sh[0];
}

__global__ void k_scanB(int nb) {
    __shared__ int sh[1024];
    int t = threadIdx.x;
    int v = (t < nb) ? g_part[t] : 0;
    sh[t] = v; __syncthreads();
    for (int off = 1; off < 1024; off <<= 1) {
        int a = (t >= off) ? sh[t - off] : 0;
        __syncthreads();
        sh[t] += a;
        __syncthreads();
    }
    if (t < nb) g_part[t] = sh[t] - v;
}

template <int SEL>
__global__ void k_scanC() {
    const int* cnt = SEL ? g_degN : g_degE;
    int* off = SEL ? g_offN : g_offE;
    const int n = SEL ? TN : TE;
    __shared__ int sh[256];
    int b = blockIdx.x, t = threadIdx.x;
    int i0 = b * 4096 + t * 16;
    int loc[16]; int s = 0;
#pragma unroll
    for (int k = 0; k < 16; k++) {
        int i = i0 + k;
        loc[k] = (i < n) ? cnt[i] : 0;
        s += loc[k];
    }
    sh[t] = s; __syncthreads();
    for (int o = 1; o < 256; o <<= 1) {
        int a = (t >= o) ? sh[t - o] : 0;
        __syncthreads();
        sh[t] += a;
        __syncthreads();
    }
    int run = g_part[b] + sh[t] - s;
#pragma unroll
    for (int k = 0; k < 16; k++) {
        int i = i0 + k;
        if (i < n) {
            off[i] = run;
            run += loc[k];
            if (i == n - 1) off[n] = run;
        }
    }
}

__global__ void k_fill(const int* __restrict__ ni, const int* __restrict__ ei) {
    int i = blockIdx.x * blockDim.x + threadIdx.x;
    if (i >= TNNZ) return;
    int t = i / NNZn;
    int n = ni[i], e = ei[i];
    int se = t * Ee + e, sn = t * Nn + n;
    int pe = atomicAdd(&g_curE[se], 1);
    g_elist[g_offE[se] + pe] = n;
    int pn = atomicAdd(&g_curN[sn], 1);
    g_nlist[g_offN[sn] + pn] = e;
}

// ---------------- weight prep ----------------
__global__ void k_prep(const float* __restrict__ Wna, const float* __restrict__ Wea,
                       const float* __restrict__ Wm1) {
    int i = blockIdx.x * blockDim.x + threadIdx.x;
    if (i < 192 * 64) {
        int c = i / 192, i3 = i % 192;
        int cp = c & 31, hi = c >> 5;
        g_wnat2[(i3 * 32 + cp) * 2 + hi] = Wna[i];
        g_weat2[(i3 * 32 + cp) * 2 + hi] = Wea[i];
    }
    if (i < 576 * 64)
        ((unsigned*)g_wm1tf4)[i] = f2tf(Wm1[i]);
}

// ---------------- layer 1 edge emb: 64 slots/block ----------------
__global__ void __launch_bounds__(256) k_e1(const float* __restrict__ W1,
                                            const float* __restrict__ b1) {
    __shared__ float sW1[16 * 64];
    __shared__ float sX[4][17];
    int tid = threadIdx.x;
    for (int j = tid; j < 1024; j += 256) sW1[j] = W1[j];
    int sl = tid >> 6, q = tid & 63;
    for (int ss = 0; ss < 16; ss++) {
        int slot = blockIdx.x * 64 + ss * 4 + sl;
        int t = slot / Ee;
        int beg = g_offE[slot], end = g_offE[slot + 1];
        float a = 0.f;
        if (q < 16) {
            for (int j = beg; j < end; j++)
                a += __ldg(g_xd + (size_t)(t * Nn + g_elist[j]) * 16 + q);
        } else if (q == 16) {
            for (int j = beg; j < end; j++)
                a += __ldg(g_dinv + t * Nn + g_elist[j]);
        }
        __syncthreads();
        if (q <= 16) sX[sl][q] = a;
        __syncthreads();
        float acc = sX[sl][16] * b1[q];
#pragma unroll
        for (int c = 0; c < 16; c++)
            acc = fmaf(sX[sl][c], sW1[c * 64 + q], acc);
        g_edge1[(size_t)slot * Hh + q] = acc * g_binv[slot];
    }
}

// ---------------- layer 2 edge emb: 64 slots/block ----------------
__global__ void __launch_bounds__(256) k_es2(const float* __restrict__ W2,
                                             const float* __restrict__ b2) {
    __shared__ float sW2[64 * 64];
    __shared__ float sV[4][65];
    __shared__ float ss2[4];
    int tid = threadIdx.x;
    for (int j = tid; j < 4096; j += 256) sW2[j] = W2[j];
    int sl = tid >> 6, h = tid & 63;
    for (int ss = 0; ss < 16; ss++) {
        int slot = blockIdx.x * 64 + ss * 4 + sl;
        int t = slot / Ee;
        int beg = g_offE[slot], end = g_offE[slot + 1];
        const float* e1base = g_edge1 + (size_t)t * Ee * Hh + h;
        float acc = 0.f;
        float s2 = 0.f;
        for (int j = beg; j < end; j++) {
            int n = g_elist[j];
            int sn = t * Nn + n;
            float d = __ldg(g_dinv + sn);
            float d2 = d * d;
            s2 += d;
            int nb = g_offN[sn], ne = g_offN[sn + 1];
            for (int jj = nb; jj < ne; jj++) {
                int ep = g_nlist[jj];
                acc = fmaf(d2, __ldg(e1base + (size_t)ep * Hh), acc);
            }
        }
        __syncthreads();
        sV[sl][h] = acc;
        if (h == 0) ss2[sl] = s2;
        __syncthreads();
        float r = ss2[sl] * b2[h];
#pragma unroll 8
        for (int c = 0; c < 64; c++)
            r = fmaf(sV[sl][c], sW2[c * 64 + h], r);
        g_es[(size_t)slot * Hh + h] = r * g_binv[slot];
    }
}

// ---------------- per-node heads ----------------
#define GN 8
#define CH 16
__global__ void __launch_bounds__(256) k_node(
        const float* __restrict__ nf,
        const float* __restrict__ bna,
        const float* __restrict__ Wt,  const float* __restrict__ bt,
        const float* __restrict__ Wr,  const float* __restrict__ br,
        const float* __restrict__ Wf,  const float* __restrict__ bf,
        float* __restrict__ out) {
    __shared__ float sx[GN][64][12];
    __shared__ u64 swc2[CH * 3 * 32];
    __shared__ float swt[3 * 192];
    __shared__ float swr[3 * 16];
    __shared__ float shv[GN][3][Tt];
    int tid = threadIdx.x;
    int g = tid >> 5, cp = tid & 31;
    int n = blockIdx.x * GN + g;

#pragma unroll
    for (int t = 0; t < Tt; t++) {
        int slot = t * Nn + n;
        int beg = g_offN[slot], end = g_offN[slot + 1];
        float d = g_dinv[slot];
        const float* src = g_es + (size_t)t * Ee * Hh;
        float a0 = 0.f, a1 = 0.f;
        for (int j = beg; j < end; j++) {
            const float* row = src + (size_t)g_nlist[j] * Hh;
            a0 += __ldg(row + cp);
            a1 += __ldg(row + cp + 32);
        }
        sx[g][cp][t]      = a0 * d;
        sx[g][cp + 32][t] = a1 * d;
    }
    for (int j = tid; j < 576; j += 256)
        swt[j] = Wt[(61 + j / 192) * 192 + (j % 192)];
    if (tid < 48) swr[tid] = Wr[(61 + tid / 16) * 16 + (tid % 16)];

    u64 acc2[9];
    {
        u64 b2 = pk2(bna[cp], bna[cp + 32]);
#pragma unroll
        for (int s = 0; s < 9; s++) acc2[s] = b2;
    }

    const u64* gw2 = (const u64*)g_wnat2;
    for (int chunk = 0; chunk < 64 / CH; chunk++) {
        __syncthreads();
        for (int j = tid; j < CH * 3 * 32; j += 256)
            swc2[j] = gw2[chunk * (CH * 3 * 32) + j];
        __syncthreads();
#pragma unroll
        for (int ii = 0; ii < CH; ii++) {
            int i = chunk * CH + ii;
            float4 x0 = *(const float4*)&sx[g][i][0];
            float4 x1 = *(const float4*)&sx[g][i][4];
            float4 x2 = *(const float4*)&sx[g][i][8];
            float xv[11] = {x0.x, x0.y, x0.z, x0.w, x1.x, x1.y, x1.z, x1.w,
                            x2.x, x2.y, x2.z};
            u64 xd[11];
#pragma unroll
            for (int s = 0; s < 11; s++) xd[s] = pk2(xv[s], xv[s]);
            u64 w0 = swc2[(ii * 3 + 0) * 32 + cp];
            u64 w1 = swc2[(ii * 3 + 1) * 32 + cp];
            u64 w2 = swc2[(ii * 3 + 2) * 32 + cp];
#pragma unroll
            for (int s = 0; s < 9; s++) {
                acc2[s] = fma2(w0, xd[s], acc2[s]);
                acc2[s] = fma2(w1, xd[s + 1], acc2[s]);
                acc2[s] = fma2(w2, xd[s + 2], acc2[s]);
            }
        }
    }
    {
        size_t b0 = ((size_t)cp * Nn + n) * 9;
        size_t b1 = ((size_t)(cp + 32) * Nn + n) * 9;
#pragma unroll
        for (int s = 0; s < 9; s++) {
            float lo, hi;
            upk2(lo, hi, acc2[s]);
            g_agg[b0 + s] = lo;
            g_agg[b1 + s] = hi;
        }
    }

    for (int u = tid; u < GN * 36; u += 256) {
        int gg = u / 36, r = u % 36;
        int o3 = r / Tt, t = r % Tt;
        int nn = blockIdx.x * GN + gg;
        float xp = bt[61 + o3];
#pragma unroll
        for (int dk = 0; dk < 3; dk++) {
            int tau = t + dk - 1;
            if (tau >= 0 && tau < Tt) {
                const float* wt = swt + o3 * 192 + dk;
#pragma unroll 8
                for (int i = 0; i < 64; i++) xp = fmaf(wt[i * 3], sx[gg][i][tau], xp);
            }
        }
        float rs = br[61 + o3];
        const float* xr = nf + ((size_t)t * Nn + nn) * CINc;
#pragma unroll
        for (int cc = 0; cc < CINc; cc++) rs = fmaf(swr[o3 * 16 + cc], xr[cc], rs);
        shv[gg][o3][t] = fmaxf(xp + rs, 0.f);
    }
    __syncthreads();
    if (tid < GN * Pp) {
        int gg = tid / Pp, pc = tid % Pp;
        int nn = blockIdx.x * GN + gg;
        float a = bf[pc];
#pragma unroll
        for (int t = 0; t < Tt; t++)
#pragma unroll
            for (int dk = 0; dk < 3; dk++)
                a = fmaf(Wf[pc * 36 + t * 3 + dk], shv[gg][dk][t], a);
        out[(size_t)nn * Pp + pc] = a;
    }
}

// ---------------- per-edge aggregator ----------------
__global__ void __launch_bounds__(256) k_eagg(const float* __restrict__ bea) {
    __shared__ float sx[GN][64][12];
    __shared__ u64 swc2[CH * 3 * 32];
    int tid = threadIdx.x;
    int g = tid >> 5, cp = tid & 31;
    int e = blockIdx.x * GN + g;

#pragma unroll
    for (int t = 0; t < 11; t++) {
        sx[g][cp][t]      = g_es[((size_t)t * Ee + e) * Hh + cp];
        sx[g][cp + 32][t] = g_es[((size_t)t * Ee + e) * Hh + cp + 32];
    }
    sx[g][cp][11] = 0.f;
    sx[g][cp + 32][11] = 0.f;

    u64 acc2[9];
    {
        u64 b2 = pk2(bea[cp], bea[cp + 32]);
#pragma unroll
        for (int s = 0; s < 9; s++) acc2[s] = b2;
    }

    const u64* gw2 = (const u64*)g_weat2;
    for (int chunk = 0; chunk < 64 / CH; chunk++) {
        __syncthreads();
        for (int j = tid; j < CH * 3 * 32; j += 256)
            swc2[j] = gw2[chunk * (CH * 3 * 32) + j];
        __syncthreads();
#pragma unroll
        for (int ii = 0; ii < CH; ii++) {
            int i = chunk * CH + ii;
            float4 x0 = *(const float4*)&sx[g][i][0];
            float4 x1 = *(const float4*)&sx[g][i][4];
            float4 x2 = *(const float4*)&sx[g][i][8];
            float xv[11] = {x0.x, x0.y, x0.z, x0.w, x1.x, x1.y, x1.z, x1.w,
                            x2.x, x2.y, x2.z};
            u64 xd[11];
#pragma unroll
            for (int s = 0; s < 11; s++) xd[s] = pk2(xv[s], xv[s]);
            u64 w0 = swc2[(ii * 3 + 0) * 32 + cp];
            u64 w1 = swc2[(ii * 3 + 1) * 32 + cp];
            u64 w2 = swc2[(ii * 3 + 2) * 32 + cp];
#pragma unroll
            for (int s = 0; s < 9; s++) {
                acc2[s] = fma2(w0, xd[s], acc2[s]);
                acc2[s] = fma2(w1, xd[s + 1], acc2[s]);
                acc2[s] = fma2(w2, xd[s + 2], acc2[s]);
            }
        }
    }
    size_t b0 = ((size_t)cp * Ee + e) * 9;
    size_t b1 = ((size_t)(cp + 32) * Ee + e) * 9;
#pragma unroll
    for (int s = 0; s < 9; s++) {
        float lo, hi;
        upk2(lo, hi, acc2[s]);
        g_eagg[b0 + s] = lo;
        g_eagg[b1 + s] = hi;
    }
}

// ---------------- score MLP: tf32 mma, 256 pairs x 64 h per block, 512 thr ----------------
__global__ void __launch_bounds__(512) k_mlp(
        const int* __restrict__ ni_full, const int* __restrict__ ei_full,
        const int* __restrict__ nni, const int* __restrict__ nei,
        const float* __restrict__ bm1,
        const float* __restrict__ Wm2, const float* __restrict__ bm2,
        float* __restrict__ out) {
    __shared__ unsigned zs[256][36];   // [pair][k-chunk32]
    __shared__ unsigned ws[32][68];    // [k][h]
    __shared__ int sn[256], se[256];
    __shared__ float sbm1[64], swm2[64];
    int tid = threadIdx.x;
    int q0 = blockIdx.x * 256;
    if (tid < 256) {
        int q = q0 + tid;
        int n, e;
        if (q < NNZn) { n = ni_full[11 * NNZn + q]; e = ei_full[11 * NNZn + q]; }
        else          { n = nni[q - NNZn];          e = nei[q - NNZn]; }
        sn[tid] = n; se[tid] = e;
    }
    if (tid < 64) { sbm1[tid] = bm1[tid]; swm2[tid] = Wm2[tid]; }
    __syncthreads();

    int w = tid >> 5;                 // warp 0..15 -> pair strip p0 = w*16
    int lane = tid & 31;
    int g = lane >> 2, tg = lane & 3;
    int p0 = w * 16;

    float acc[8][4];
#pragma unroll
    for (int nt = 0; nt < 8; nt++)
#pragma unroll
        for (int j = 0; j < 4; j++) acc[nt][j] = 0.f;

    const float4* ag4 = (const float4*)g_agg;
    const float4* eg4 = (const float4*)g_eagg;
    int p = tid & 255, half = tid >> 8;    // staging: each (p,half) stages 16 k
    int an = sn[p] * 144, ae = se[p] * 144;

    for (int c = 0; c < 18; c++) {         // 18 chunks of 32 k
        __syncthreads();
        // stage weights: 512 uint4 total, one per thread
        {
            uint4 t4 = g_wm1tf4[c * 512 + tid];
            int k = tid >> 4, h4 = tid & 15;
            *(uint4*)&ws[k][h4 * 4] = t4;
        }
        // stage z = agg .* eagg (tf32): 16 k per (p,half)
        {
            int base = an + c * 8 + half * 4;
            int ebase = ae + c * 8 + half * 4;
#pragma unroll
            for (int j = 0; j < 4; j++) {
                float4 a = ag4[base + j];
                float4 b = eg4[ebase + j];
                uint4 t4 = make_uint4(f2tf(a.x * b.x), f2tf(a.y * b.y),
                                      f2tf(a.z * b.z), f2tf(a.w * b.w));
                *(uint4*)&zs[p][half * 16 + j * 4] = t4;
            }
        }
        __syncthreads();
#pragma unroll
        for (int s = 0; s < 4; s++) {
            int kk = s * 8;
            unsigned a0 = zs[p0 + g][kk + tg];
            unsigned a1 = zs[p0 + g + 8][kk + tg];
            unsigned a2 = zs[p0 + g][kk + tg + 4];
            unsigned a3 = zs[p0 + g + 8][kk + tg + 4];
#pragma unroll
            for (int nt = 0; nt < 8; nt++) {
                unsigned b0 = ws[kk + tg][nt * 8 + g];
                unsigned b1 = ws[kk + tg + 4][nt * 8 + g];
                mma_tf32(acc[nt][0], acc[nt][1], acc[nt][2], acc[nt][3],
                         a0, a1, a2, a3, b0, b1);
            }
        }
    }

    // epilogue: relu(+bm1) * Wm2, quad shuffle-reduce over h
    float sum0 = 0.f, sum1 = 0.f;
#pragma unroll
    for (int nt = 0; nt < 8; nt++) {
        int h0 = nt * 8 + 2 * tg;
        float b0 = sbm1[h0], b1 = sbm1[h0 + 1];
        float w0 = swm2[h0], w1 = swm2[h0 + 1];
        sum0 += fmaxf(acc[nt][0] + b0, 0.f) * w0 + fmaxf(acc[nt][1] + b1, 0.f) * w1;
        sum1 += fmaxf(acc[nt][2] + b0, 0.f) * w0 + fmaxf(acc[nt][3] + b1, 0.f) * w1;
    }
    sum0 += __shfl_xor_sync(0xffffffffu, sum0, 1);
    sum0 += __shfl_xor_sync(0xffffffffu, sum0, 2);
    sum1 += __shfl_xor_sync(0xffffffffu, sum1, 1);
    sum1 += __shfl_xor_sync(0xffffffffu, sum1, 2);
    if (tg == 0) {
        float bb = bm2[0];
        out[(size_t)Nn * Pp + q0 + p0 + g] = sum0 + bb;
        out[(size_t)Nn * Pp + q0 + p0 + g + 8] = sum1 + bb;
    }
}

// ---------------- host launcher ----------------
extern "C" void kernel_launch(void* const* d_in, const int* in_sizes, int n_in,
                              void* d_out, int out_size) {
    const float* nf  = (const float*)d_in[0];
    const float* W1  = (const float*)d_in[1];
    const float* b1  = (const float*)d_in[2];
    const float* W2  = (const float*)d_in[3];
    const float* b2  = (const float*)d_in[4];
    const float* Wt  = (const float*)d_in[5];
    const float* bt  = (const float*)d_in[6];
    const float* Wr  = (const float*)d_in[7];
    const float* br  = (const float*)d_in[8];
    const float* Wf  = (const float*)d_in[9];
    const float* bf  = (const float*)d_in[10];
    const float* Wna = (const float*)d_in[11];
    const float* bna = (const float*)d_in[12];
    const float* Wea = (const float*)d_in[13];
    const float* bea = (const float*)d_in[14];
    const float* Wm1 = (const float*)d_in[15];
    const float* bm1 = (const float*)d_in[16];
    const float* Wm2 = (const float*)d_in[17];
    const float* bm2 = (const float*)d_in[18];
    const int* node_idx = (const int*)d_in[19];
    const int* edge_idx = (const int*)d_in[20];
    const int* nni = (const int*)d_in[21];
    const int* nei = (const int*)d_in[22];
    float* out = (float*)d_out;

    int nbE = (TE + 4095) / 4096;
    int nbN = (TN + 4095) / 4096;

    k_zero<<<2048, 256>>>();
    k_count<<<(TNNZ + 255) / 256, 256>>>(node_idx, edge_idx);
    k_inv<<<(TN + 255) / 256, 256>>>();
    k_xd<<<(TN * 4 + 255) / 256, 256>>>(nf);
    k_scanA<0><<<nbE, 256>>>();
    k_scanB<<<1, 1024>>>(nbE);
    k_scanC<0><<<nbE, 256>>>();
    k_scanA<1><<<nbN, 256>>>();
    k_scanB<<<1, 1024>>>(nbN);
    k_scanC<1><<<nbN, 256>>>();
    k_fill<<<(TNNZ + 255) / 256, 256>>>(node_idx, edge_idx);
    k_prep<<<(576 * 64 + 255) / 256, 256>>>(Wna, Wea, Wm1);

    k_e1<<<TE / 64, 256>>>(W1, b1);
    k_es2<<<TE / 64, 256>>>(W2, b2);

    k_node<<<Nn / GN, 256>>>(nf, bna, Wt, bt, Wr, br, Wf, bf, out);
    k_eagg<<<Ee / GN, 256>>>(bea);
    k_mlp<<<(2 * NNZn) / 256, 512>>>(node_idx, edge_idx, nni, nei, bm1, Wm2, bm2, out);
}

// round 13
// speedup vs baseline: 1.0454x; 1.0454x over previous
#include <cuda_runtime.h>

#define Tt   12
#define Nn   100000
#define CINc 16
#define Ee   20000
#define NNZn 160000
#define Hh   64
#define Pp   12

#define TN   (Tt * Nn)
#define TE   (Tt * Ee)
#define TNNZ (Tt * NNZn)

typedef unsigned long long u64;

// ---- f32x2 packed helpers ----
__device__ __forceinline__ u64 pk2(float lo, float hi) {
    u64 r;
    asm("mov.b64 %0, {%1, %2};" : "=l"(r) : "f"(lo), "f"(hi));
    return r;
}
__device__ __forceinline__ void upk2(float& lo, float& hi, u64 v) {
    asm("mov.b64 {%0, %1}, %2;" : "=f"(lo), "=f"(hi) : "l"(v));
}
__device__ __forceinline__ u64 fma2(u64 a, u64 b, u64 c) {
    u64 d;
    asm("fma.rn.f32x2 %0, %1, %2, %3;" : "=l"(d) : "l"(a), "l"(b), "l"(c));
    return d;
}
// ---- tf32 helpers ----
__device__ __forceinline__ unsigned f2tf(float f) {
    unsigned r;
    asm("cvt.rna.tf32.f32 %0, %1;" : "=r"(r) : "f"(f));
    return r;
}
__device__ __forceinline__ void mma_tf32(float& c0, float& c1, float& c2, float& c3,
                                         unsigned a0, unsigned a1, unsigned a2, unsigned a3,
                                         unsigned b0, unsigned b1) {
    asm volatile(
        "mma.sync.aligned.m16n8k8.row.col.f32.tf32.tf32.f32 "
        "{%0,%1,%2,%3}, {%4,%5,%6,%7}, {%8,%9}, {%0,%1,%2,%3};"
        : "+f"(c0), "+f"(c1), "+f"(c2), "+f"(c3)
        : "r"(a0), "r"(a1), "r"(a2), "r"(a3), "r"(b0), "r"(b1));
}

// ---------------- scratch ----------------
__device__ float g_es[(size_t)TE * Hh];
__device__ float g_edge1[(size_t)TE * Hh];
__device__ float g_agg[(size_t)Hh * Nn * 9];
__device__ float g_eagg[(size_t)Hh * Ee * 9];
__device__ float g_dinv[TN];
__device__ float g_binv[TE];
__device__ float g_wnat2[192 * 64];
__device__ float g_weat2[192 * 64];
__device__ uint4 g_wm1tf4[576 * 64 / 4];

__device__ int g_degN[TN];
__device__ int g_degE[TE];
__device__ int g_offN[TN + 1];
__device__ int g_offE[TE + 1];
__device__ int g_curN[TN];
__device__ int g_curE[TE];
__device__ int g_nlist[TNNZ];
__device__ int g_elist[TNNZ];
__device__ int g_part[1024];

// ---------------- zero ----------------
__global__ void k_zero() {
    int i = blockIdx.x * blockDim.x + threadIdx.x;
    int stride = gridDim.x * blockDim.x;
    for (int j = i; j < TN; j += stride) { g_degN[j] = 0; g_curN[j] = 0; }
    for (int j = i; j < TE; j += stride) { g_degE[j] = 0; g_curE[j] = 0; }
}

__global__ void k_count(const int* __restrict__ ni, const int* __restrict__ ei) {
    int i = blockIdx.x * blockDim.x + threadIdx.x;
    if (i >= TNNZ) return;
    int t = i / NNZn;
    atomicAdd(&g_degN[t * Nn + ni[i]], 1);
    atomicAdd(&g_degE[t * Ee + ei[i]], 1);
}

__global__ void k_inv() {
    int i = blockIdx.x * blockDim.x + threadIdx.x;
    if (i < TN) { int d = g_degN[i]; g_dinv[i] = d > 0 ? rsqrtf((float)d) : 0.f; }
    if (i < TE) { int c = g_degE[i]; g_binv[i] = c > 0 ? 1.f / (float)c : 0.f; }
}

// ---------------- scans ----------------
template <int SEL>
__global__ void k_scanA() {
    const int* cnt = SEL ? g_degN : g_degE;
    const int n = SEL ? TN : TE;
    __shared__ int sh[256];
    int b = blockIdx.x, t = threadIdx.x;
    int i0 = b * 4096 + t * 16;
    int s = 0;
#pragma unroll
    for (int k = 0; k < 16; k++) { int i = i0 + k; if (i < n) s += cnt[i]; }
    sh[t] = s; __syncthreads();
    for (int off = 128; off; off >>= 1) {
        if (t < off) sh[t] += sh[t + off];
        __syncthreads();
    }
    if (t == 0) g_part[b] = sh[0];
}

__global__ void k_scanB(int nb) {
    __shared__ int sh[1024];
    int t = threadIdx.x;
    int v = (t < nb) ? g_part[t] : 0;
    sh[t] = v; __syncthreads();
    for (int off = 1; off < 1024; off <<= 1) {
        int a = (t >= off) ? sh[t - off] : 0;
        __syncthreads();
        sh[t] += a;
        __syncthreads();
    }
    if (t < nb) g_part[t] = sh[t] - v;
}

template <int SEL>
__global__ void k_scanC() {
    const int* cnt = SEL ? g_degN : g_degE;
    int* off = SEL ? g_offN : g_offE;
    const int n = SEL ? TN : TE;
    __shared__ int sh[256];
    int b = blockIdx.x, t = threadIdx.x;
    int i0 = b * 4096 + t * 16;
    int loc[16]; int s = 0;
#pragma unroll
    for (int k = 0; k < 16; k++) {
        int i = i0 + k;
        loc[k] = (i < n) ? cnt[i] : 0;
        s += loc[k];
    }
    sh[t] = s; __syncthreads();
    for (int o = 1; o < 256; o <<= 1) {
        int a = (t >= o) ? sh[t - o] : 0;
        __syncthreads();
        sh[t] += a;
        __syncthreads();
    }
    int run = g_part[b] + sh[t] - s;
#pragma unroll
    for (int k = 0; k < 16; k++) {
        int i = i0 + k;
        if (i < n) {
            off[i] = run;
            run += loc[k];
            if (i == n - 1) off[n] = run;
        }
    }
}

__global__ void k_fill(const int* __restrict__ ni, const int* __restrict__ ei) {
    int i = blockIdx.x * blockDim.x + threadIdx.x;
    if (i >= TNNZ) return;
    int t = i / NNZn;
    int n = ni[i], e = ei[i];
    int se = t * Ee + e, sn = t * Nn + n;
    int pe = atomicAdd(&g_curE[se], 1);
    g_elist[g_offE[se] + pe] = n;
    int pn = atomicAdd(&g_curN[sn], 1);
    g_nlist[g_offN[sn] + pn] = e;
}

// ---------------- weight prep ----------------
__global__ void k_prep(const float* __restrict__ Wna, const float* __restrict__ Wea,
                       const float* __restrict__ Wm1) {
    int i = blockIdx.x * blockDim.x + threadIdx.x;
    if (i < 192 * 64) {
        int c = i / 192, i3 = i % 192;
        int cp = c & 31, hi = c >> 5;
        g_wnat2[(i3 * 32 + cp) * 2 + hi] = Wna[i];
        g_weat2[(i3 * 32 + cp) * 2 + hi] = Wea[i];
    }
    if (i < 576 * 64)
        ((unsigned*)g_wm1tf4)[i] = f2tf(Wm1[i]);
}

// ---------------- layer 1 edge emb: 16 slots/block (x*dinv folded in) ----------------
__global__ void __launch_bounds__(256) k_e1(const float* __restrict__ nf,
                                            const float* __restrict__ W1,
                                            const float* __restrict__ b1) {
    __shared__ float sW1[16 * 64];
    __shared__ float sX[4][17];
    int tid = threadIdx.x;
    for (int j = tid; j < 1024; j += 256) sW1[j] = W1[j];
    int sl = tid >> 6, q = tid & 63;
#pragma unroll
    for (int ss = 0; ss < 4; ss++) {
        int slot = blockIdx.x * 16 + ss * 4 + sl;
        int t = slot / Ee;
        int beg = g_offE[slot], end = g_offE[slot + 1];
        float a = 0.f;
        if (q < 16) {
            for (int j = beg; j < end; j++) {
                int sn = t * Nn + g_elist[j];
                float d = __ldg(g_dinv + sn);
                a = fmaf(d, __ldg(nf + (size_t)sn * 16 + q), a);
            }
        } else if (q == 16) {
            for (int j = beg; j < end; j++)
                a += __ldg(g_dinv + t * Nn + g_elist[j]);
        }
        __syncthreads();
        if (q <= 16) sX[sl][q] = a;
        __syncthreads();
        float acc = sX[sl][16] * b1[q];
#pragma unroll
        for (int c = 0; c < 16; c++)
            acc = fmaf(sX[sl][c], sW1[c * 64 + q], acc);
        g_edge1[(size_t)slot * Hh + q] = acc * g_binv[slot];
    }
}

// ---------------- layer 2 edge emb: 16 slots/block ----------------
__global__ void __launch_bounds__(256) k_es2(const float* __restrict__ W2,
                                             const float* __restrict__ b2) {
    __shared__ float sW2[64 * 64];
    __shared__ float sV[4][65];
    __shared__ float ss2[4];
    int tid = threadIdx.x;
    for (int j = tid; j < 4096; j += 256) sW2[j] = W2[j];
    int sl = tid >> 6, h = tid & 63;
#pragma unroll
    for (int ss = 0; ss < 4; ss++) {
        int slot = blockIdx.x * 16 + ss * 4 + sl;
        int t = slot / Ee;
        int beg = g_offE[slot], end = g_offE[slot + 1];
        const float* e1base = g_edge1 + (size_t)t * Ee * Hh + h;
        float acc = 0.f;
        float s2 = 0.f;
        for (int j = beg; j < end; j++) {
            int n = g_elist[j];
            int sn = t * Nn + n;
            float d = __ldg(g_dinv + sn);
            float d2 = d * d;
            s2 += d;
            int nb = g_offN[sn], ne = g_offN[sn + 1];
            for (int jj = nb; jj < ne; jj++) {
                int ep = g_nlist[jj];
                acc = fmaf(d2, __ldg(e1base + (size_t)ep * Hh), acc);
            }
        }
        __syncthreads();
        sV[sl][h] = acc;
        if (h == 0) ss2[sl] = s2;
        __syncthreads();
        float r = ss2[sl] * b2[h];
#pragma unroll 8
        for (int c = 0; c < 64; c++)
            r = fmaf(sV[sl][c], sW2[c * 64 + h], r);
        g_es[(size_t)slot * Hh + h] = r * g_binv[slot];
    }
}

// ---------------- per-node heads ----------------
#define GN 8
#define CH 8
__global__ void __launch_bounds__(256) k_node(
        const float* __restrict__ nf,
        const float* __restrict__ bna,
        const float* __restrict__ Wt,  const float* __restrict__ bt,
        const float* __restrict__ Wr,  const float* __restrict__ br,
        const float* __restrict__ Wf,  const float* __restrict__ bf,
        float* __restrict__ out) {
    __shared__ float sx[GN][64][12];
    __shared__ u64 swc2[CH * 3 * 32];
    __shared__ float swt[3 * 192];
    __shared__ float swr[3 * 16];
    __shared__ float shv[GN][3][Tt];
    int tid = threadIdx.x;
    int g = tid >> 5, cp = tid & 31;
    int n = blockIdx.x * GN + g;

#pragma unroll
    for (int t = 0; t < Tt; t++) {
        int slot = t * Nn + n;
        int beg = g_offN[slot], end = g_offN[slot + 1];
        float d = g_dinv[slot];
        const float* src = g_es + (size_t)t * Ee * Hh;
        float a0 = 0.f, a1 = 0.f;
        for (int j = beg; j < end; j++) {
            const float* row = src + (size_t)g_nlist[j] * Hh;
            a0 += __ldg(row + cp);
            a1 += __ldg(row + cp + 32);
        }
        sx[g][cp][t]      = a0 * d;
        sx[g][cp + 32][t] = a1 * d;
    }
    for (int j = tid; j < 576; j += 256)
        swt[j] = Wt[(61 + j / 192) * 192 + (j % 192)];
    if (tid < 48) swr[tid] = Wr[(61 + tid / 16) * 16 + (tid % 16)];

    u64 acc2[9];
    {
        u64 b2 = pk2(bna[cp], bna[cp + 32]);
#pragma unroll
        for (int s = 0; s < 9; s++) acc2[s] = b2;
    }

    const u64* gw2 = (const u64*)g_wnat2;
    for (int chunk = 0; chunk < 64 / CH; chunk++) {
        __syncthreads();
        for (int j = tid; j < CH * 3 * 32; j += 256)
            swc2[j] = gw2[chunk * (CH * 3 * 32) + j];
        __syncthreads();
#pragma unroll
        for (int ii = 0; ii < CH; ii++) {
            int i = chunk * CH + ii;
            float4 x0 = *(const float4*)&sx[g][i][0];
            float4 x1 = *(const float4*)&sx[g][i][4];
            float4 x2 = *(const float4*)&sx[g][i][8];
            float xv[11] = {x0.x, x0.y, x0.z, x0.w, x1.x, x1.y, x1.z, x1.w,
                            x2.x, x2.y, x2.z};
            u64 xd[11];
#pragma unroll
            for (int s = 0; s < 11; s++) xd[s] = pk2(xv[s], xv[s]);
            u64 w0 = swc2[(ii * 3 + 0) * 32 + cp];
            u64 w1 = swc2[(ii * 3 + 1) * 32 + cp];
            u64 w2 = swc2[(ii * 3 + 2) * 32 + cp];
#pragma unroll
            for (int s = 0; s < 9; s++) {
                acc2[s] = fma2(w0, xd[s], acc2[s]);
                acc2[s] = fma2(w1, xd[s + 1], acc2[s]);
                acc2[s] = fma2(w2, xd[s + 2], acc2[s]);
            }
        }
    }
    {
        size_t b0 = ((size_t)cp * Nn + n) * 9;
        size_t b1 = ((size_t)(cp + 32) * Nn + n) * 9;
#pragma unroll
        for (int s = 0; s < 9; s++) {
            float lo, hi;
            upk2(lo, hi, acc2[s]);
            g_agg[b0 + s] = lo;
            g_agg[b1 + s] = hi;
        }
    }

    for (int u = tid; u < GN * 36; u += 256) {
        int gg = u / 36, r = u % 36;
        int o3 = r / Tt, t = r % Tt;
        int nn = blockIdx.x * GN + gg;
        float xp = bt[61 + o3];
#pragma unroll
        for (int dk = 0; dk < 3; dk++) {
            int tau = t + dk - 1;
            if (tau >= 0 && tau < Tt) {
                const float* wt = swt + o3 * 192 + dk;
#pragma unroll 8
                for (int i = 0; i < 64; i++) xp = fmaf(wt[i * 3], sx[gg][i][tau], xp);
            }
        }
        float rs = br[61 + o3];
        const float* xr = nf + ((size_t)t * Nn + nn) * CINc;
#pragma unroll
        for (int cc = 0; cc < CINc; cc++) rs = fmaf(swr[o3 * 16 + cc], xr[cc], rs);
        shv[gg][o3][t] = fmaxf(xp + rs, 0.f);
    }
    __syncthreads();
    if (tid < GN * Pp) {
        int gg = tid / Pp, pc = tid % Pp;
        int nn = blockIdx.x * GN + gg;
        float a = bf[pc];
#pragma unroll
        for (int t = 0; t < Tt; t++)
#pragma unroll
            for (int dk = 0; dk < 3; dk++)
                a = fmaf(Wf[pc * 36 + t * 3 + dk], shv[gg][dk][t], a);
        out[(size_t)nn * Pp + pc] = a;
    }
}

// ---------------- per-edge aggregator ----------------
__global__ void __launch_bounds__(256) k_eagg(const float* __restrict__ bea) {
    __shared__ float sx[GN][64][12];
    __shared__ u64 swc2[CH * 3 * 32];
    int tid = threadIdx.x;
    int g = tid >> 5, cp = tid & 31;
    int e = blockIdx.x * GN + g;

#pragma unroll
    for (int t = 0; t < 11; t++) {
        sx[g][cp][t]      = g_es[((size_t)t * Ee + e) * Hh + cp];
        sx[g][cp + 32][t] = g_es[((size_t)t * Ee + e) * Hh + cp + 32];
    }
    sx[g][cp][11] = 0.f;
    sx[g][cp + 32][11] = 0.f;

    u64 acc2[9];
    {
        u64 b2 = pk2(bea[cp], bea[cp + 32]);
#pragma unroll
        for (int s = 0; s < 9; s++) acc2[s] = b2;
    }

    const u64* gw2 = (const u64*)g_weat2;
    for (int chunk = 0; chunk < 64 / CH; chunk++) {
        __syncthreads();
        for (int j = tid; j < CH * 3 * 32; j += 256)
            swc2[j] = gw2[chunk * (CH * 3 * 32) + j];
        __syncthreads();
#pragma unroll
        for (int ii = 0; ii < CH; ii++) {
            int i = chunk * CH + ii;
            float4 x0 = *(const float4*)&sx[g][i][0];
            float4 x1 = *(const float4*)&sx[g][i][4];
            float4 x2 = *(const float4*)&sx[g][i][8];
            float xv[11] = {x0.x, x0.y, x0.z, x0.w, x1.x, x1.y, x1.z, x1.w,
                            x2.x, x2.y, x2.z};
            u64 xd[11];
#pragma unroll
            for (int s = 0; s < 11; s++) xd[s] = pk2(xv[s], xv[s]);
            u64 w0 = swc2[(ii * 3 + 0) * 32 + cp];
            u64 w1 = swc2[(ii * 3 + 1) * 32 + cp];
            u64 w2 = swc2[(ii * 3 + 2) * 32 + cp];
#pragma unroll
            for (int s = 0; s < 9; s++) {
                acc2[s] = fma2(w0, xd[s], acc2[s]);
                acc2[s] = fma2(w1, xd[s + 1], acc2[s]);
                acc2[s] = fma2(w2, xd[s + 2], acc2[s]);
            }
        }
    }
    size_t b0 = ((size_t)cp * Ee + e) * 9;
    size_t b1 = ((size_t)(cp + 32) * Ee + e) * 9;
#pragma unroll
    for (int s = 0; s < 9; s++) {
        float lo, hi;
        upk2(lo, hi, acc2[s]);
        g_eagg[b0 + s] = lo;
        g_eagg[b1 + s] = hi;
    }
}

// ---------------- score MLP: tf32 mma, 128 pairs x 64 h per block, 256 thr ----------------
__global__ void __launch_bounds__(256) k_mlp(
        const int* __restrict__ ni_full, const int* __restrict__ ei_full,
        const int* __restrict__ nni, const int* __restrict__ nei,
        const float* __restrict__ bm1,
        const float* __restrict__ Wm2, const float* __restrict__ bm2,
        float* __restrict__ out) {
    __shared__ unsigned zs[128][36];   // [pair][k-chunk32]
    __shared__ unsigned ws[32][68];    // [k][h]
    __shared__ int sn[128], se[128];
    __shared__ float sbm1[64], swm2[64];
    int tid = threadIdx.x;
    int q0 = blockIdx.x * 128;
    if (tid < 128) {
        int q = q0 + tid;
        int n, e;
        if (q < NNZn) { n = ni_full[11 * NNZn + q]; e = ei_full[11 * NNZn + q]; }
        else          { n = nni[q - NNZn];          e = nei[q - NNZn]; }
        sn[tid] = n; se[tid] = e;
    }
    if (tid < 64) { sbm1[tid] = bm1[tid]; swm2[tid] = Wm2[tid]; }
    __syncthreads();

    int w = tid >> 5;                 // warp 0..7 -> pair strip p0 = w*16
    int lane = tid & 31;
    int g = lane >> 2, tg = lane & 3;
    int p0 = w * 16;

    float acc[8][4];
#pragma unroll
    for (int nt = 0; nt < 8; nt++)
#pragma unroll
        for (int j = 0; j < 4; j++) acc[nt][j] = 0.f;

    const float4* ag4 = (const float4*)g_agg;
    const float4* eg4 = (const float4*)g_eagg;
    int p = tid & 127, half = tid >> 7;    // staging: each (p,half) stages 16 k
    int an = sn[p] * 144, ae = se[p] * 144;

    for (int c = 0; c < 18; c++) {         // 18 chunks of 32 k
        __syncthreads();
        for (int j = tid; j < 512; j += 256) {
            uint4 t4 = g_wm1tf4[c * 512 + j];
            int k = j >> 4, h4 = j & 15;
            *(uint4*)&ws[k][h4 * 4] = t4;
        }
        {
            int base = an + c * 8 + half * 4;
            int ebase = ae + c * 8 + half * 4;
#pragma unroll
            for (int j = 0; j < 4; j++) {
                float4 a = ag4[base + j];
                float4 b = eg4[ebase + j];
                uint4 t4 = make_uint4(f2tf(a.x * b.x), f2tf(a.y * b.y),
                                      f2tf(a.z * b.z), f2tf(a.w * b.w));
                *(uint4*)&zs[p][half * 16 + j * 4] = t4;
            }
        }
        __syncthreads();
#pragma unroll
        for (int s = 0; s < 4; s++) {
            int kk = s * 8;
            unsigned a0 = zs[p0 + g][kk + tg];
            unsigned a1 = zs[p0 + g + 8][kk + tg];
            unsigned a2 = zs[p0 + g][kk + tg + 4];
            unsigned a3 = zs[p0 + g + 8][kk + tg + 4];
#pragma unroll
            for (int nt = 0; nt < 8; nt++) {
                unsigned b0 = ws[kk + tg][nt * 8 + g];
                unsigned b1 = ws[kk + tg + 4][nt * 8 + g];
                mma_tf32(acc[nt][0], acc[nt][1], acc[nt][2], acc[nt][3],
                         a0, a1, a2, a3, b0, b1);
            }
        }
    }

    float sum0 = 0.f, sum1 = 0.f;
#pragma unroll
    for (int nt = 0; nt < 8; nt++) {
        int h0 = nt * 8 + 2 * tg;
        float b0 = sbm1[h0], b1 = sbm1[h0 + 1];
        float w0 = swm2[h0], w1 = swm2[h0 + 1];
        sum0 += fmaxf(acc[nt][0] + b0, 0.f) * w0 + fmaxf(acc[nt][1] + b1, 0.f) * w1;
        sum1 += fmaxf(acc[nt][2] + b0, 0.f) * w0 + fmaxf(acc[nt][3] + b1, 0.f) * w1;
    }
    sum0 += __shfl_xor_sync(0xffffffffu, sum0, 1);
    sum0 += __shfl_xor_sync(0xffffffffu, sum0, 2);
    sum1 += __shfl_xor_sync(0xffffffffu, sum1, 1);
    sum1 += __shfl_xor_sync(0xffffffffu, sum1, 2);
    if (tg == 0) {
        float bb = bm2[0];
        out[(size_t)Nn * Pp + q0 + p0 + g] = sum0 + bb;
        out[(size_t)Nn * Pp + q0 + p0 + g + 8] = sum1 + bb;
    }
}

// ---------------- host launcher ----------------
extern "C" void kernel_launch(void* const* d_in, const int* in_sizes, int n_in,
                              void* d_out, int out_size) {
    const float* nf  = (const float*)d_in[0];
    const float* W1  = (const float*)d_in[1];
    const float* b1  = (const float*)d_in[2];
    const float* W2  = (const float*)d_in[3];
    const float* b2  = (const float*)d_in[4];
    const float* Wt  = (const float*)d_in[5];
    const float* bt  = (const float*)d_in[6];
    const float* Wr  = (const float*)d_in[7];
    const float* br  = (const float*)d_in[8];
    const float* Wf  = (const float*)d_in[9];
    const float* bf  = (const float*)d_in[10];
    const float* Wna = (const float*)d_in[11];
    const float* bna = (const float*)d_in[12];
    const float* Wea = (const float*)d_in[13];
    const float* bea = (const float*)d_in[14];
    const float* Wm1 = (const float*)d_in[15];
    const float* bm1 = (const float*)d_in[16];
    const float* Wm2 = (const float*)d_in[17];
    const float* bm2 = (const float*)d_in[18];
    const int* node_idx = (const int*)d_in[19];
    const int* edge_idx = (const int*)d_in[20];
    const int* nni = (const int*)d_in[21];
    const int* nei = (const int*)d_in[22];
    float* out = (float*)d_out;

    int nbE = (TE + 4095) / 4096;
    int nbN = (TN + 4095) / 4096;

    k_zero<<<2048, 256>>>();
    k_count<<<(TNNZ + 255) / 256, 256>>>(node_idx, edge_idx);
    k_inv<<<(TN + 255) / 256, 256>>>();
    k_scanA<0><<<nbE, 256>>>();
    k_scanB<<<1, 1024>>>(nbE);
    k_scanC<0><<<nbE, 256>>>();
    k_scanA<1><<<nbN, 256>>>();
    k_scanB<<<1, 1024>>>(nbN);
    k_scanC<1><<<nbN, 256>>>();
    k_fill<<<(TNNZ + 255) / 256, 256>>>(node_idx, edge_idx);
    k_prep<<<(576 * 64 + 255) / 256, 256>>>(Wna, Wea, Wm1);

    k_e1<<<TE / 16, 256>>>(nf, W1, b1);
    k_es2<<<TE / 16, 256>>>(W2, b2);

    k_node<<<Nn / GN, 256>>>(nf, bna, Wt, bt, Wr, br, Wf, bf, out);
    k_eagg<<<Ee / GN, 256>>>(bea);
    k_mlp<<<(2 * NNZn) / 128, 256>>>(node_idx, edge_idx, nni, nei, bm1, Wm2, bm2, out);
}

// round 14
// speedup vs baseline: 1.1039x; 1.0559x over previous
#include <cuda_runtime.h>

#define Tt   12
#define Nn   100000
#define CINc 16
#define Ee   20000
#define NNZn 160000
#define Hh   64
#define Pp   12

#define TN   (Tt * Nn)
#define TE   (Tt * Ee)
#define TNNZ (Tt * NNZn)

typedef unsigned long long u64;

// ---- f32x2 packed helpers ----
__device__ __forceinline__ u64 pk2(float lo, float hi) {
    u64 r;
    asm("mov.b64 %0, {%1, %2};" : "=l"(r) : "f"(lo), "f"(hi));
    return r;
}
__device__ __forceinline__ void upk2(float& lo, float& hi, u64 v) {
    asm("mov.b64 {%0, %1}, %2;" : "=f"(lo), "=f"(hi) : "l"(v));
}
__device__ __forceinline__ u64 fma2(u64 a, u64 b, u64 c) {
    u64 d;
    asm("fma.rn.f32x2 %0, %1, %2, %3;" : "=l"(d) : "l"(a), "l"(b), "l"(c));
    return d;
}
// ---- tf32 helpers ----
__device__ __forceinline__ unsigned f2tf(float f) {
    unsigned r;
    asm("cvt.rna.tf32.f32 %0, %1;" : "=r"(r) : "f"(f));
    return r;
}
__device__ __forceinline__ void mma_tf32(float& c0, float& c1, float& c2, float& c3,
                                         unsigned a0, unsigned a1, unsigned a2, unsigned a3,
                                         unsigned b0, unsigned b1) {
    asm volatile(
        "mma.sync.aligned.m16n8k8.row.col.f32.tf32.tf32.f32 "
        "{%0,%1,%2,%3}, {%4,%5,%6,%7}, {%8,%9}, {%0,%1,%2,%3};"
        : "+f"(c0), "+f"(c1), "+f"(c2), "+f"(c3)
        : "r"(a0), "r"(a1), "r"(a2), "r"(a3), "r"(b0), "r"(b1));
}

// ---------------- scratch ----------------
__device__ float g_es[(size_t)TE * Hh];
__device__ float g_edge1[(size_t)TE * Hh];
__device__ float g_agg[(size_t)Hh * Nn * 9];
__device__ float g_eagg[(size_t)Hh * Ee * 9];
__device__ float g_dinv[TN];
__device__ float g_binv[TE];
__device__ unsigned g_wnatf[192 * 64];   // Wna^T as tf32 bits [k=(i,dk)][c]
__device__ float g_weat2[192 * 64];      // Wea packed pairs (FFMA2 path, k_eagg)
__device__ uint4 g_wm1tf4[576 * 64 / 4];

__device__ int g_degN[TN];
__device__ int g_degE[TE];
__device__ int g_offN[TN + 1];
__device__ int g_offE[TE + 1];
__device__ int g_curN[TN];
__device__ int g_curE[TE];
__device__ int g_nlist[TNNZ];
__device__ int g_elist[TNNZ];
__device__ int g_part[1024];

// ---------------- zero ----------------
__global__ void k_zero() {
    int i = blockIdx.x * blockDim.x + threadIdx.x;
    int stride = gridDim.x * blockDim.x;
    for (int j = i; j < TN; j += stride) { g_degN[j] = 0; g_curN[j] = 0; }
    for (int j = i; j < TE; j += stride) { g_degE[j] = 0; g_curE[j] = 0; }
}

__global__ void k_count(const int* __restrict__ ni, const int* __restrict__ ei) {
    int i = blockIdx.x * blockDim.x + threadIdx.x;
    if (i >= TNNZ) return;
    int t = i / NNZn;
    atomicAdd(&g_degN[t * Nn + ni[i]], 1);
    atomicAdd(&g_degE[t * Ee + ei[i]], 1);
}

__global__ void k_inv() {
    int i = blockIdx.x * blockDim.x + threadIdx.x;
    if (i < TN) { int d = g_degN[i]; g_dinv[i] = d > 0 ? rsqrtf((float)d) : 0.f; }
    if (i < TE) { int c = g_degE[i]; g_binv[i] = c > 0 ? 1.f / (float)c : 0.f; }
}

// ---------------- scans ----------------
template <int SEL>
__global__ void k_scanA() {
    const int* cnt = SEL ? g_degN : g_degE;
    const int n = SEL ? TN : TE;
    __shared__ int sh[256];
    int b = blockIdx.x, t = threadIdx.x;
    int i0 = b * 4096 + t * 16;
    int s = 0;
#pragma unroll
    for (int k = 0; k < 16; k++) { int i = i0 + k; if (i < n) s += cnt[i]; }
    sh[t] = s; __syncthreads();
    for (int off = 128; off; off >>= 1) {
        if (t < off) sh[t] += sh[t + off];
        __syncthreads();
    }
    if (t == 0) g_part[b] = sh[0];
}

__global__ void k_scanB(int nb) {
    __shared__ int sh[1024];
    int t = threadIdx.x;
    int v = (t < nb) ? g_part[t] : 0;
    sh[t] = v; __syncthreads();
    for (int off = 1; off < 1024; off <<= 1) {
        int a = (t >= off) ? sh[t - off] : 0;
        __syncthreads();
        sh[t] += a;
        __syncthreads();
    }
    if (t < nb) g_part[t] = sh[t] - v;
}

template <int SEL>
__global__ void k_scanC() {
    const int* cnt = SEL ? g_degN : g_degE;
    int* off = SEL ? g_offN : g_offE;
    const int n = SEL ? TN : TE;
    __shared__ int sh[256];
    int b = blockIdx.x, t = threadIdx.x;
    int i0 = b * 4096 + t * 16;
    int loc[16]; int s = 0;
#pragma unroll
    for (int k = 0; k < 16; k++) {
        int i = i0 + k;
        loc[k] = (i < n) ? cnt[i] : 0;
        s += loc[k];
    }
    sh[t] = s; __syncthreads();
    for (int o = 1; o < 256; o <<= 1) {
        int a = (t >= o) ? sh[t - o] : 0;
        __syncthreads();
        sh[t] += a;
        __syncthreads();
    }
    int run = g_part[b] + sh[t] - s;
#pragma unroll
    for (int k = 0; k < 16; k++) {
        int i = i0 + k;
        if (i < n) {
            off[i] = run;
            run += loc[k];
            if (i == n - 1) off[n] = run;
        }
    }
}

__global__ void k_fill(const int* __restrict__ ni, const int* __restrict__ ei) {
    int i = blockIdx.x * blockDim.x + threadIdx.x;
    if (i >= TNNZ) return;
    int t = i / NNZn;
    int n = ni[i], e = ei[i];
    int se = t * Ee + e, sn = t * Nn + n;
    int pe = atomicAdd(&g_curE[se], 1);
    g_elist[g_offE[se] + pe] = n;
    int pn = atomicAdd(&g_curN[sn], 1);
    g_nlist[g_offN[sn] + pn] = e;
}

// ---------------- weight prep ----------------
__global__ void k_prep(const float* __restrict__ Wna, const float* __restrict__ Wea,
                       const float* __restrict__ Wm1) {
    int i = blockIdx.x * blockDim.x + threadIdx.x;
    if (i < 192 * 64) {
        int c = i / 192, i3 = i % 192;
        int cp = c & 31, hi = c >> 5;
        g_weat2[(i3 * 32 + cp) * 2 + hi] = Wea[i];
        g_wnatf[i3 * 64 + c] = f2tf(Wna[i]);
    }
    if (i < 576 * 64)
        ((unsigned*)g_wm1tf4)[i] = f2tf(Wm1[i]);
}

// ---------------- layer 1 edge emb: 16 slots/block (x*dinv folded in) ----------------
__global__ void __launch_bounds__(256) k_e1(const float* __restrict__ nf,
                                            const float* __restrict__ W1,
                                            const float* __restrict__ b1) {
    __shared__ float sW1[16 * 64];
    __shared__ float sX[4][17];
    int tid = threadIdx.x;
    for (int j = tid; j < 1024; j += 256) sW1[j] = W1[j];
    int sl = tid >> 6, q = tid & 63;
#pragma unroll
    for (int ss = 0; ss < 4; ss++) {
        int slot = blockIdx.x * 16 + ss * 4 + sl;
        int t = slot / Ee;
        int beg = g_offE[slot], end = g_offE[slot + 1];
        float a = 0.f;
        if (q < 16) {
            for (int j = beg; j < end; j++) {
                int sn = t * Nn + g_elist[j];
                float d = __ldg(g_dinv + sn);
                a = fmaf(d, __ldg(nf + (size_t)sn * 16 + q), a);
            }
        } else if (q == 16) {
            for (int j = beg; j < end; j++)
                a += __ldg(g_dinv + t * Nn + g_elist[j]);
        }
        __syncthreads();
        if (q <= 16) sX[sl][q] = a;
        __syncthreads();
        float acc = sX[sl][16] * b1[q];
#pragma unroll
        for (int c = 0; c < 16; c++)
            acc = fmaf(sX[sl][c], sW1[c * 64 + q], acc);
        g_edge1[(size_t)slot * Hh + q] = acc * g_binv[slot];
    }
}

// ---------------- layer 2 edge emb: 16 slots/block ----------------
__global__ void __launch_bounds__(256) k_es2(const float* __restrict__ W2,
                                             const float* __restrict__ b2) {
    __shared__ float sW2[64 * 64];
    __shared__ float sV[4][65];
    __shared__ float ss2[4];
    int tid = threadIdx.x;
    for (int j = tid; j < 4096; j += 256) sW2[j] = W2[j];
    int sl = tid >> 6, h = tid & 63;
#pragma unroll
    for (int ss = 0; ss < 4; ss++) {
        int slot = blockIdx.x * 16 + ss * 4 + sl;
        int t = slot / Ee;
        int beg = g_offE[slot], end = g_offE[slot + 1];
        const float* e1base = g_edge1 + (size_t)t * Ee * Hh + h;
        float acc = 0.f;
        float s2 = 0.f;
        for (int j = beg; j < end; j++) {
            int n = g_elist[j];
            int sn = t * Nn + n;
            float d = __ldg(g_dinv + sn);
            float d2 = d * d;
            s2 += d;
            int nb = g_offN[sn], ne = g_offN[sn + 1];
            for (int jj = nb; jj < ne; jj++) {
                int ep = g_nlist[jj];
                acc = fmaf(d2, __ldg(e1base + (size_t)ep * Hh), acc);
            }
        }
        __syncthreads();
        sV[sl][h] = acc;
        if (h == 0) ss2[sl] = s2;
        __syncthreads();
        float r = ss2[sl] * b2[h];
#pragma unroll 8
        for (int c = 0; c < 64; c++)
            r = fmaf(sV[sl][c], sW2[c * 64 + h], r);
        g_es[(size_t)slot * Hh + h] = r * g_binv[slot];
    }
}

// ---------------- per-node heads: aggregator conv via tf32 mma ----------------
#define GN 8
__global__ void __launch_bounds__(256) k_node(
        const float* __restrict__ nf,
        const float* __restrict__ bna,
        const float* __restrict__ Wt,  const float* __restrict__ bt,
        const float* __restrict__ Wr,  const float* __restrict__ br,
        const float* __restrict__ Wf,  const float* __restrict__ bf,
        float* __restrict__ out) {
    __shared__ float sx[GN][64][12];      // tf32-rounded fp32, 24 KB
    __shared__ unsigned ws[48][68];       // W chunk [k][c] tf32, 12.75 KB
    __shared__ float swt[3 * 192];
    __shared__ float swr[3 * 16];
    __shared__ float shv[GN][3][Tt];
    __shared__ float sbna[64];
    int tid = threadIdx.x;
    int g = tid >> 5, cp = tid & 31;
    int n = blockIdx.x * GN + g;

    // gather xs rows from g_es via CSR; round to tf32 at store
#pragma unroll
    for (int t = 0; t < Tt; t++) {
        int slot = t * Nn + n;
        int beg = g_offN[slot], end = g_offN[slot + 1];
        float d = g_dinv[slot];
        const float* src = g_es + (size_t)t * Ee * Hh;
        float a0 = 0.f, a1 = 0.f;
        for (int j = beg; j < end; j++) {
            const float* row = src + (size_t)g_nlist[j] * Hh;
            a0 += __ldg(row + cp);
            a1 += __ldg(row + cp + 32);
        }
        sx[g][cp][t]      = __uint_as_float(f2tf(a0 * d));
        sx[g][cp + 32][t] = __uint_as_float(f2tf(a1 * d));
    }
    for (int j = tid; j < 576; j += 256)
        swt[j] = Wt[(61 + j / 192) * 192 + (j % 192)];
    if (tid < 48) swr[tid] = Wr[(61 + tid / 16) * 16 + (tid % 16)];
    if (tid < 64) sbna[tid] = bna[tid];

    // ---- conv GEMM: rows (n,s) 0..71 (pad 80), K=192 (i,dk), N=64 c ----
    int w = tid >> 5;            // warp -> n-tile (8 c each)
    int lane = tid & 31;
    int gq = lane >> 2, tg = lane & 3;
    int rn0[5], rs0[5], rn1[5], rs1[5];
    bool v0[5], v1[5];
#pragma unroll
    for (int mt = 0; mt < 5; mt++) {
        int r0 = mt * 16 + gq, r1 = r0 + 8;
        rn0[mt] = r0 / 9; rs0[mt] = r0 % 9; v0[mt] = r0 < 72;
        rn1[mt] = r1 / 9; rs1[mt] = r1 % 9; v1[mt] = r1 < 72;
    }
    float acc[5][4];
#pragma unroll
    for (int mt = 0; mt < 5; mt++)
#pragma unroll
        for (int j = 0; j < 4; j++) acc[mt][j] = 0.f;

    const unsigned* sxu = (const unsigned*)sx;   // flat [(n*64+i)*12 + tau]

    for (int chunk = 0; chunk < 4; chunk++) {
        __syncthreads();     // (chunk 0: also orders sx gather before A reads)
        for (int j = tid; j < 3072; j += 256)
            ws[j >> 6][j & 63] = g_wnatf[chunk * 3072 + j];
        __syncthreads();
#pragma unroll
        for (int kt = 0; kt < 6; kt++) {
            int k0 = chunk * 48 + kt * 8 + tg;
            int k1 = k0 + 4;
            int i0 = k0 / 3, d0 = k0 - i0 * 3;
            int i1 = k1 / 3, d1 = k1 - i1 * 3;
            int kk = kt * 8;
            unsigned b0 = ws[kk + tg][w * 8 + gq];
            unsigned b1 = ws[kk + tg + 4][w * 8 + gq];
#pragma unroll
            for (int mt = 0; mt < 5; mt++) {
                unsigned a0 = v0[mt] ? sxu[(rn0[mt] * 64 + i0) * 12 + rs0[mt] + d0] : 0u;
                unsigned a1 = v1[mt] ? sxu[(rn1[mt] * 64 + i0) * 12 + rs1[mt] + d0] : 0u;
                unsigned a2 = v0[mt] ? sxu[(rn0[mt] * 64 + i1) * 12 + rs0[mt] + d1] : 0u;
                unsigned a3 = v1[mt] ? sxu[(rn1[mt] * 64 + i1) * 12 + rs1[mt] + d1] : 0u;
                mma_tf32(acc[mt][0], acc[mt][1], acc[mt][2], acc[mt][3],
                         a0, a1, a2, a3, b0, b1);
            }
        }
    }

    // write agg (+bias). C layout: c0=C[g][2tg], c1=C[g][2tg+1], c2/c3 rows +8
    {
        int c0 = w * 8 + 2 * tg, c1 = c0 + 1;
        float bb0 = sbna[c0], bb1 = sbna[c1];
        int nb = blockIdx.x * GN;
#pragma unroll
        for (int mt = 0; mt < 5; mt++) {
            if (v0[mt]) {
                int nn = nb + rn0[mt];
                g_agg[((size_t)c0 * Nn + nn) * 9 + rs0[mt]] = acc[mt][0] + bb0;
                g_agg[((size_t)c1 * Nn + nn) * 9 + rs0[mt]] = acc[mt][1] + bb1;
            }
            if (v1[mt]) {
                int nn = nb + rn1[mt];
                g_agg[((size_t)c0 * Nn + nn) * 9 + rs1[mt]] = acc[mt][2] + bb0;
                g_agg[((size_t)c1 * Nn + nn) * 9 + rs1[mt]] = acc[mt][3] + bb1;
            }
        }
    }

    // temporal conv + residual + relu (channels 61..63)
    for (int u = tid; u < GN * 36; u += 256) {
        int gg = u / 36, r = u % 36;
        int o3 = r / Tt, t = r % Tt;
        int nn = blockIdx.x * GN + gg;
        float xp = bt[61 + o3];
#pragma unroll
        for (int dk = 0; dk < 3; dk++) {
            int tau = t + dk - 1;
            if (tau >= 0 && tau < Tt) {
                const float* wt = swt + o3 * 192 + dk;
#pragma unroll 8
                for (int i = 0; i < 64; i++) xp = fmaf(wt[i * 3], sx[gg][i][tau], xp);
            }
        }
        float rs = br[61 + o3];
        const float* xr = nf + ((size_t)t * Nn + nn) * CINc;
#pragma unroll
        for (int cc = 0; cc < CINc; cc++) rs = fmaf(swr[o3 * 16 + cc], xr[cc], rs);
        shv[gg][o3][t] = fmaxf(xp + rs, 0.f);
    }
    __syncthreads();
    if (tid < GN * Pp) {
        int gg = tid / Pp, pc = tid % Pp;
        int nn = blockIdx.x * GN + gg;
        float a = bf[pc];
#pragma unroll
        for (int t = 0; t < Tt; t++)
#pragma unroll
            for (int dk = 0; dk < 3; dk++)
                a = fmaf(Wf[pc * 36 + t * 3 + dk], shv[gg][dk][t], a);
        out[(size_t)nn * Pp + pc] = a;
    }
}

// ---------------- per-edge aggregator (FFMA2 path, unchanged) ----------------
#define CH 8
__global__ void __launch_bounds__(256) k_eagg(const float* __restrict__ bea) {
    __shared__ float sx[GN][64][12];
    __shared__ u64 swc2[CH * 3 * 32];
    int tid = threadIdx.x;
    int g = tid >> 5, cp = tid & 31;
    int e = blockIdx.x * GN + g;

#pragma unroll
    for (int t = 0; t < 11; t++) {
        sx[g][cp][t]      = g_es[((size_t)t * Ee + e) * Hh + cp];
        sx[g][cp + 32][t] = g_es[((size_t)t * Ee + e) * Hh + cp + 32];
    }
    sx[g][cp][11] = 0.f;
    sx[g][cp + 32][11] = 0.f;

    u64 acc2[9];
    {
        u64 b2 = pk2(bea[cp], bea[cp + 32]);
#pragma unroll
        for (int s = 0; s < 9; s++) acc2[s] = b2;
    }

    const u64* gw2 = (const u64*)g_weat2;
    for (int chunk = 0; chunk < 64 / CH; chunk++) {
        __syncthreads();
        for (int j = tid; j < CH * 3 * 32; j += 256)
            swc2[j] = gw2[chunk * (CH * 3 * 32) + j];
        __syncthreads();
#pragma unroll
        for (int ii = 0; ii < CH; ii++) {
            int i = chunk * CH + ii;
            float4 x0 = *(const float4*)&sx[g][i][0];
            float4 x1 = *(const float4*)&sx[g][i][4];
            float4 x2 = *(const float4*)&sx[g][i][8];
            float xv[11] = {x0.x, x0.y, x0.z, x0.w, x1.x, x1.y, x1.z, x1.w,
                            x2.x, x2.y, x2.z};
            u64 xd[11];
#pragma unroll
            for (int s = 0; s < 11; s++) xd[s] = pk2(xv[s], xv[s]);
            u64 w0 = swc2[(ii * 3 + 0) * 32 + cp];
            u64 w1 = swc2[(ii * 3 + 1) * 32 + cp];
            u64 w2 = swc2[(ii * 3 + 2) * 32 + cp];
#pragma unroll
            for (int s = 0; s < 9; s++) {
                acc2[s] = fma2(w0, xd[s], acc2[s]);
                acc2[s] = fma2(w1, xd[s + 1], acc2[s]);
                acc2[s] = fma2(w2, xd[s + 2], acc2[s]);
            }
        }
    }
    size_t b0 = ((size_t)cp * Ee + e) * 9;
    size_t b1 = ((size_t)(cp + 32) * Ee + e) * 9;
#pragma unroll
    for (int s = 0; s < 9; s++) {
        float lo, hi;
        upk2(lo, hi, acc2[s]);
        g_eagg[b0 + s] = lo;
        g_eagg[b1 + s] = hi;
    }
}

// ---------------- score MLP: tf32 mma, 128 pairs x 64 h per block, 256 thr ----------------
__global__ void __launch_bounds__(256) k_mlp(
        const int* __restrict__ ni_full, const int* __restrict__ ei_full,
        const int* __restrict__ nni, const int* __restrict__ nei,
        const float* __restrict__ bm1,
        const float* __restrict__ Wm2, const float* __restrict__ bm2,
        float* __restrict__ out) {
    __shared__ unsigned zs[128][36];
    __shared__ unsigned ws[32][68];
    __shared__ int sn[128], se[128];
    __shared__ float sbm1[64], swm2[64];
    int tid = threadIdx.x;
    int q0 = blockIdx.x * 128;
    if (tid < 128) {
        int q = q0 + tid;
        int n, e;
        if (q < NNZn) { n = ni_full[11 * NNZn + q]; e = ei_full[11 * NNZn + q]; }
        else          { n = nni[q - NNZn];          e = nei[q - NNZn]; }
        sn[tid] = n; se[tid] = e;
    }
    if (tid < 64) { sbm1[tid] = bm1[tid]; swm2[tid] = Wm2[tid]; }
    __syncthreads();

    int w = tid >> 5;
    int lane = tid & 31;
    int g = lane >> 2, tg = lane & 3;
    int p0 = w * 16;

    float acc[8][4];
#pragma unroll
    for (int nt = 0; nt < 8; nt++)
#pragma unroll
        for (int j = 0; j < 4; j++) acc[nt][j] = 0.f;

    const float4* ag4 = (const float4*)g_agg;
    const float4* eg4 = (const float4*)g_eagg;
    int p = tid & 127, half = tid >> 7;
    int an = sn[p] * 144, ae = se[p] * 144;

    for (int c = 0; c < 18; c++) {
        __syncthreads();
        for (int j = tid; j < 512; j += 256) {
            uint4 t4 = g_wm1tf4[c * 512 + j];
            int k = j >> 4, h4 = j & 15;
            *(uint4*)&ws[k][h4 * 4] = t4;
        }
        {
            int base = an + c * 8 + half * 4;
            int ebase = ae + c * 8 + half * 4;
#pragma unroll
            for (int j = 0; j < 4; j++) {
                float4 a = ag4[base + j];
                float4 b = eg4[ebase + j];
                uint4 t4 = make_uint4(f2tf(a.x * b.x), f2tf(a.y * b.y),
                                      f2tf(a.z * b.z), f2tf(a.w * b.w));
                *(uint4*)&zs[p][half * 16 + j * 4] = t4;
            }
        }
        __syncthreads();
#pragma unroll
        for (int s = 0; s < 4; s++) {
            int kk = s * 8;
            unsigned a0 = zs[p0 + g][kk + tg];
            unsigned a1 = zs[p0 + g + 8][kk + tg];
            unsigned a2 = zs[p0 + g][kk + tg + 4];
            unsigned a3 = zs[p0 + g + 8][kk + tg + 4];
#pragma unroll
            for (int nt = 0; nt < 8; nt++) {
                unsigned b0 = ws[kk + tg][nt * 8 + g];
                unsigned b1 = ws[kk + tg + 4][nt * 8 + g];
                mma_tf32(acc[nt][0], acc[nt][1], acc[nt][2], acc[nt][3],
                         a0, a1, a2, a3, b0, b1);
            }
        }
    }

    float sum0 = 0.f, sum1 = 0.f;
#pragma unroll
    for (int nt = 0; nt < 8; nt++) {
        int h0 = nt * 8 + 2 * tg;
        float b0 = sbm1[h0], b1 = sbm1[h0 + 1];
        float w0 = swm2[h0], w1 = swm2[h0 + 1];
        sum0 += fmaxf(acc[nt][0] + b0, 0.f) * w0 + fmaxf(acc[nt][1] + b1, 0.f) * w1;
        sum1 += fmaxf(acc[nt][2] + b0, 0.f) * w0 + fmaxf(acc[nt][3] + b1, 0.f) * w1;
    }
    sum0 += __shfl_xor_sync(0xffffffffu, sum0, 1);
    sum0 += __shfl_xor_sync(0xffffffffu, sum0, 2);
    sum1 += __shfl_xor_sync(0xffffffffu, sum1, 1);
    sum1 += __shfl_xor_sync(0xffffffffu, sum1, 2);
    if (tg == 0) {
        float bb = bm2[0];
        out[(size_t)Nn * Pp + q0 + p0 + g] = sum0 + bb;
        out[(size_t)Nn * Pp + q0 + p0 + g + 8] = sum1 + bb;
    }
}

// ---------------- host launcher ----------------
extern "C" void kernel_launch(void* const* d_in, const int* in_sizes, int n_in,
                              void* d_out, int out_size) {
    const float* nf  = (const float*)d_in[0];
    const float* W1  = (const float*)d_in[1];
    const float* b1  = (const float*)d_in[2];
    const float* W2  = (const float*)d_in[3];
    const float* b2  = (const float*)d_in[4];
    const float* Wt  = (const float*)d_in[5];
    const float* bt  = (const float*)d_in[6];
    const float* Wr  = (const float*)d_in[7];
    const float* br  = (const float*)d_in[8];
    const float* Wf  = (const float*)d_in[9];
    const float* bf  = (const float*)d_in[10];
    const float* Wna = (const float*)d_in[11];
    const float* bna = (const float*)d_in[12];
    const float* Wea = (const float*)d_in[13];
    const float* bea = (const float*)d_in[14];
    const float* Wm1 = (const float*)d_in[15];
    const float* bm1 = (const float*)d_in[16];
    const float* Wm2 = (const float*)d_in[17];
    const float* bm2 = (const float*)d_in[18];
    const int* node_idx = (const int*)d_in[19];
    const int* edge_idx = (const int*)d_in[20];
    const int* nni = (const int*)d_in[21];
    const int* nei = (const int*)d_in[22];
    float* out = (float*)d_out;

    int nbE = (TE + 4095) / 4096;
    int nbN = (TN + 4095) / 4096;

    k_zero<<<2048, 256>>>();
    k_count<<<(TNNZ + 255) / 256, 256>>>(node_idx, edge_idx);
    k_inv<<<(TN + 255) / 256, 256>>>();
    k_scanA<0><<<nbE, 256>>>();
    k_scanB<<<1, 1024>>>(nbE);
    k_scanC<0><<<nbE, 256>>>();
    k_scanA<1><<<nbN, 256>>>();
    k_scanB<<<1, 1024>>>(nbN);
    k_scanC<1><<<nbN, 256>>>();
    k_fill<<<(TNNZ + 255) / 256, 256>>>(node_idx, edge_idx);
    k_prep<<<(576 * 64 + 255) / 256, 256>>>(Wna, Wea, Wm1);

    k_e1<<<TE / 16, 256>>>(nf, W1, b1);
    k_es2<<<TE / 16, 256>>>(W2, b2);

    k_node<<<Nn / GN, 256>>>(nf, bna, Wt, bt, Wr, br, Wf, bf, out);
    k_eagg<<<Ee / GN, 256>>>(bea);
    k_mlp<<<(2 * NNZn) / 128, 256>>>(node_idx, edge_idx, nni, nei, bm1, Wm2, bm2, out);
}

// round 15
// speedup vs baseline: 1.1083x; 1.0040x over previous
#include <cuda_runtime.h>

#define Tt   12
#define Nn   100000
#define CINc 16
#define Ee   20000
#define NNZn 160000
#define Hh   64
#define Pp   12

#define TN   (Tt * Nn)
#define TE   (Tt * Ee)
#define TNNZ (Tt * NNZn)

#define GN   8
#define NBN  (Nn / GN)   // 12500 node blocks
#define NBE  (Ee / GN)   // 2500 edge blocks

typedef unsigned long long u64;

// ---- tf32 helpers ----
__device__ __forceinline__ unsigned f2tf(float f) {
    unsigned r;
    asm("cvt.rna.tf32.f32 %0, %1;" : "=r"(r) : "f"(f));
    return r;
}
__device__ __forceinline__ void mma_tf32(float& c0, float& c1, float& c2, float& c3,
                                         unsigned a0, unsigned a1, unsigned a2, unsigned a3,
                                         unsigned b0, unsigned b1) {
    asm volatile(
        "mma.sync.aligned.m16n8k8.row.col.f32.tf32.tf32.f32 "
        "{%0,%1,%2,%3}, {%4,%5,%6,%7}, {%8,%9}, {%0,%1,%2,%3};"
        : "+f"(c0), "+f"(c1), "+f"(c2), "+f"(c3)
        : "r"(a0), "r"(a1), "r"(a2), "r"(a3), "r"(b0), "r"(b1));
}

// ---------------- scratch ----------------
__device__ float g_es[(size_t)TE * Hh];
__device__ float g_edge1[(size_t)TE * Hh];
__device__ float g_agg[(size_t)Hh * Nn * 9];
__device__ float g_eagg[(size_t)Hh * Ee * 9];
__device__ float g_dinv[TN];
__device__ float g_binv[TE];
__device__ unsigned g_wnatf[192 * 64];   // Wna^T tf32 [k=(i,dk)][c]
__device__ unsigned g_weatf[192 * 64];   // Wea^T tf32 [k=(i,dk)][c]
__device__ uint4 g_wm1tf4[576 * 64 / 4];

__device__ int g_degN[TN];
__device__ int g_degE[TE];
__device__ int g_offN[TN + 1];
__device__ int g_offE[TE + 1];
__device__ int g_curN[TN];
__device__ int g_curE[TE];
__device__ int g_nlist[TNNZ];
__device__ int g_elist[TNNZ];
__device__ int g_part[1024];

// ---------------- zero ----------------
__global__ void k_zero() {
    int i = blockIdx.x * blockDim.x + threadIdx.x;
    int stride = gridDim.x * blockDim.x;
    for (int j = i; j < TN; j += stride) { g_degN[j] = 0; g_curN[j] = 0; }
    for (int j = i; j < TE; j += stride) { g_degE[j] = 0; g_curE[j] = 0; }
}

__global__ void k_count(const int* __restrict__ ni, const int* __restrict__ ei) {
    int i = blockIdx.x * blockDim.x + threadIdx.x;
    if (i >= TNNZ) return;
    int t = i / NNZn;
    atomicAdd(&g_degN[t * Nn + ni[i]], 1);
    atomicAdd(&g_degE[t * Ee + ei[i]], 1);
}

__global__ void k_inv() {
    int i = blockIdx.x * blockDim.x + threadIdx.x;
    if (i < TN) { int d = g_degN[i]; g_dinv[i] = d > 0 ? rsqrtf((float)d) : 0.f; }
    if (i < TE) { int c = g_degE[i]; g_binv[i] = c > 0 ? 1.f / (float)c : 0.f; }
}

// ---------------- scans ----------------
template <int SEL>
__global__ void k_scanA() {
    const int* cnt = SEL ? g_degN : g_degE;
    const int n = SEL ? TN : TE;
    __shared__ int sh[256];
    int b = blockIdx.x, t = threadIdx.x;
    int i0 = b * 4096 + t * 16;
    int s = 0;
#pragma unroll
    for (int k = 0; k < 16; k++) { int i = i0 + k; if (i < n) s += cnt[i]; }
    sh[t] = s; __syncthreads();
    for (int off = 128; off; off >>= 1) {
        if (t < off) sh[t] += sh[t + off];
        __syncthreads();
    }
    if (t == 0) g_part[b] = sh[0];
}

__global__ void k_scanB(int nb) {
    __shared__ int sh[1024];
    int t = threadIdx.x;
    int v = (t < nb) ? g_part[t] : 0;
    sh[t] = v; __syncthreads();
    for (int off = 1; off < 1024; off <<= 1) {
        int a = (t >= off) ? sh[t - off] : 0;
        __syncthreads();
        sh[t] += a;
        __syncthreads();
    }
    if (t < nb) g_part[t] = sh[t] - v;
}

template <int SEL>
__global__ void k_scanC() {
    const int* cnt = SEL ? g_degN : g_degE;
    int* off = SEL ? g_offN : g_offE;
    const int n = SEL ? TN : TE;
    __shared__ int sh[256];
    int b = blockIdx.x, t = threadIdx.x;
    int i0 = b * 4096 + t * 16;
    int loc[16]; int s = 0;
#pragma unroll
    for (int k = 0; k < 16; k++) {
        int i = i0 + k;
        loc[k] = (i < n) ? cnt[i] : 0;
        s += loc[k];
    }
    sh[t] = s; __syncthreads();
    for (int o = 1; o < 256; o <<= 1) {
        int a = (t >= o) ? sh[t - o] : 0;
        __syncthreads();
        sh[t] += a;
        __syncthreads();
    }
    int run = g_part[b] + sh[t] - s;
#pragma unroll
    for (int k = 0; k < 16; k++) {
        int i = i0 + k;
        if (i < n) {
            off[i] = run;
            run += loc[k];
            if (i == n - 1) off[n] = run;
        }
    }
}

__global__ void k_fill(const int* __restrict__ ni, const int* __restrict__ ei) {
    int i = blockIdx.x * blockDim.x + threadIdx.x;
    if (i >= TNNZ) return;
    int t = i / NNZn;
    int n = ni[i], e = ei[i];
    int se = t * Ee + e, sn = t * Nn + n;
    int pe = atomicAdd(&g_curE[se], 1);
    g_elist[g_offE[se] + pe] = n;
    int pn = atomicAdd(&g_curN[sn], 1);
    g_nlist[g_offN[sn] + pn] = e;
}

// ---------------- weight prep ----------------
__global__ void k_prep(const float* __restrict__ Wna, const float* __restrict__ Wea,
                       const float* __restrict__ Wm1) {
    int i = blockIdx.x * blockDim.x + threadIdx.x;
    if (i < 192 * 64) {
        int c = i / 192, i3 = i % 192;
        g_wnatf[i3 * 64 + c] = f2tf(Wna[i]);
        g_weatf[i3 * 64 + c] = f2tf(Wea[i]);
    }
    if (i < 576 * 64)
        ((unsigned*)g_wm1tf4)[i] = f2tf(Wm1[i]);
}

// ---------------- layer 1 edge emb: 16 slots/block (x*dinv folded in) ----------------
__global__ void __launch_bounds__(256) k_e1(const float* __restrict__ nf,
                                            const float* __restrict__ W1,
                                            const float* __restrict__ b1) {
    __shared__ float sW1[16 * 64];
    __shared__ float sX[4][17];
    int tid = threadIdx.x;
    for (int j = tid; j < 1024; j += 256) sW1[j] = W1[j];
    int sl = tid >> 6, q = tid & 63;
#pragma unroll
    for (int ss = 0; ss < 4; ss++) {
        int slot = blockIdx.x * 16 + ss * 4 + sl;
        int t = slot / Ee;
        int beg = g_offE[slot], end = g_offE[slot + 1];
        float a = 0.f;
        if (q < 16) {
            for (int j = beg; j < end; j++) {
                int sn = t * Nn + g_elist[j];
                float d = __ldg(g_dinv + sn);
                a = fmaf(d, __ldg(nf + (size_t)sn * 16 + q), a);
            }
        } else if (q == 16) {
            for (int j = beg; j < end; j++)
                a += __ldg(g_dinv + t * Nn + g_elist[j]);
        }
        __syncthreads();
        if (q <= 16) sX[sl][q] = a;
        __syncthreads();
        float acc = sX[sl][16] * b1[q];
#pragma unroll
        for (int c = 0; c < 16; c++)
            acc = fmaf(sX[sl][c], sW1[c * 64 + q], acc);
        g_edge1[(size_t)slot * Hh + q] = acc * g_binv[slot];
    }
}

// ---------------- layer 2 edge emb: 16 slots/block ----------------
__global__ void __launch_bounds__(256) k_es2(const float* __restrict__ W2,
                                             const float* __restrict__ b2) {
    __shared__ float sW2[64 * 64];
    __shared__ float sV[4][65];
    __shared__ float ss2[4];
    int tid = threadIdx.x;
    for (int j = tid; j < 4096; j += 256) sW2[j] = W2[j];
    int sl = tid >> 6, h = tid & 63;
#pragma unroll
    for (int ss = 0; ss < 4; ss++) {
        int slot = blockIdx.x * 16 + ss * 4 + sl;
        int t = slot / Ee;
        int beg = g_offE[slot], end = g_offE[slot + 1];
        const float* e1base = g_edge1 + (size_t)t * Ee * Hh + h;
        float acc = 0.f;
        float s2 = 0.f;
        for (int j = beg; j < end; j++) {
            int n = g_elist[j];
            int sn = t * Nn + n;
            float d = __ldg(g_dinv + sn);
            float d2 = d * d;
            s2 += d;
            int nb = g_offN[sn], ne = g_offN[sn + 1];
            for (int jj = nb; jj < ne; jj++) {
                int ep = g_nlist[jj];
                acc = fmaf(d2, __ldg(e1base + (size_t)ep * Hh), acc);
            }
        }
        __syncthreads();
        sV[sl][h] = acc;
        if (h == 0) ss2[sl] = s2;
        __syncthreads();
        float r = ss2[sl] * b2[h];
#pragma unroll 8
        for (int c = 0; c < 64; c++)
            r = fmaf(sV[sl][c], sW2[c * 64 + h], r);
        g_es[(size_t)slot * Hh + h] = r * g_binv[slot];
    }
}

// ---------------- merged heads: node blocks [0,NBN), edge blocks [NBN,NBN+NBE) --
__global__ void __launch_bounds__(256) k_heads(
        const float* __restrict__ nf,
        const float* __restrict__ bna,  const float* __restrict__ bea,
        const float* __restrict__ Wt,  const float* __restrict__ bt,
        const float* __restrict__ Wr,  const float* __restrict__ br,
        const float* __restrict__ Wf,  const float* __restrict__ bf,
        float* __restrict__ out) {
    __shared__ float sx[GN][64][12];      // 24 KB
    __shared__ unsigned ws[48][68];       // 12.75 KB
    __shared__ float swt[3 * 192];
    __shared__ float swr[3 * 16];
    __shared__ float shv[GN][3][Tt];
    __shared__ float sbias[64];
    int tid = threadIdx.x;
    int g = tid >> 5, cp = tid & 31;
    bool isNode = blockIdx.x < NBN;

    if (isNode) {
        int n = blockIdx.x * GN + g;
        // gather xs rows from g_es via CSR; round to tf32 at store
#pragma unroll
        for (int t = 0; t < Tt; t++) {
            int slot = t * Nn + n;
            int beg = g_offN[slot], end = g_offN[slot + 1];
            float d = g_dinv[slot];
            const float* src = g_es + (size_t)t * Ee * Hh;
            float a0 = 0.f, a1 = 0.f;
            for (int j = beg; j < end; j++) {
                const float* row = src + (size_t)g_nlist[j] * Hh;
                a0 += __ldg(row + cp);
                a1 += __ldg(row + cp + 32);
            }
            sx[g][cp][t]      = __uint_as_float(f2tf(a0 * d));
            sx[g][cp + 32][t] = __uint_as_float(f2tf(a1 * d));
        }
        for (int j = tid; j < 576; j += 256)
            swt[j] = Wt[(61 + j / 192) * 192 + (j % 192)];
        if (tid < 48) swr[tid] = Wr[(61 + tid / 16) * 16 + (tid % 16)];
        if (tid < 64) sbias[tid] = bna[tid];
    } else {
        int e = (blockIdx.x - NBN) * GN + g;
        // direct load of edge embeddings (11 taus; tau 11 zero)
#pragma unroll
        for (int t = 0; t < 11; t++) {
            sx[g][cp][t]      = __uint_as_float(f2tf(g_es[((size_t)t * Ee + e) * Hh + cp]));
            sx[g][cp + 32][t] = __uint_as_float(f2tf(g_es[((size_t)t * Ee + e) * Hh + cp + 32]));
        }
        sx[g][cp][11] = 0.f;
        sx[g][cp + 32][11] = 0.f;
        if (tid < 64) sbias[tid] = bea[tid];
    }

    // ---- conv GEMM: rows (row,s) 0..71 (pad 80), K=192 (i,dk), N=64 c ----
    int w = tid >> 5;
    int lane = tid & 31;
    int gq = lane >> 2, tg = lane & 3;
    int rn0[5], rs0[5], rn1[5], rs1[5];
    bool v0[5], v1[5];
#pragma unroll
    for (int mt = 0; mt < 5; mt++) {
        int r0 = mt * 16 + gq, r1 = r0 + 8;
        rn0[mt] = r0 / 9; rs0[mt] = r0 % 9; v0[mt] = r0 < 72;
        rn1[mt] = r1 / 9; rs1[mt] = r1 % 9; v1[mt] = r1 < 72;
    }
    float acc[5][4];
#pragma unroll
    for (int mt = 0; mt < 5; mt++)
#pragma unroll
        for (int j = 0; j < 4; j++) acc[mt][j] = 0.f;

    const unsigned* sxu = (const unsigned*)sx;
    const unsigned* gwf = isNode ? g_wnatf : g_weatf;

    for (int chunk = 0; chunk < 4; chunk++) {
        __syncthreads();
        for (int j = tid; j < 3072; j += 256)
            ws[j >> 6][j & 63] = gwf[chunk * 3072 + j];
        __syncthreads();
#pragma unroll
        for (int kt = 0; kt < 6; kt++) {
            int k0 = chunk * 48 + kt * 8 + tg;
            int k1 = k0 + 4;
            int i0 = k0 / 3, d0 = k0 - i0 * 3;
            int i1 = k1 / 3, d1 = k1 - i1 * 3;
            int kk = kt * 8;
            unsigned b0 = ws[kk + tg][w * 8 + gq];
            unsigned b1 = ws[kk + tg + 4][w * 8 + gq];
#pragma unroll
            for (int mt = 0; mt < 5; mt++) {
                unsigned a0 = v0[mt] ? sxu[(rn0[mt] * 64 + i0) * 12 + rs0[mt] + d0] : 0u;
                unsigned a1 = v1[mt] ? sxu[(rn1[mt] * 64 + i0) * 12 + rs1[mt] + d0] : 0u;
                unsigned a2 = v0[mt] ? sxu[(rn0[mt] * 64 + i1) * 12 + rs0[mt] + d1] : 0u;
                unsigned a3 = v1[mt] ? sxu[(rn1[mt] * 64 + i1) * 12 + rs1[mt] + d1] : 0u;
                mma_tf32(acc[mt][0], acc[mt][1], acc[mt][2], acc[mt][3],
                         a0, a1, a2, a3, b0, b1);
            }
        }
    }

    // write agg/eagg (+bias). C layout: c0=C[g][2tg], c1=+1, c2/c3 rows +8
    {
        int c0 = w * 8 + 2 * tg, c1 = c0 + 1;
        float bb0 = sbias[c0], bb1 = sbias[c1];
        if (isNode) {
            int nb = blockIdx.x * GN;
#pragma unroll
            for (int mt = 0; mt < 5; mt++) {
                if (v0[mt]) {
                    int nn = nb + rn0[mt];
                    g_agg[((size_t)c0 * Nn + nn) * 9 + rs0[mt]] = acc[mt][0] + bb0;
                    g_agg[((size_t)c1 * Nn + nn) * 9 + rs0[mt]] = acc[mt][1] + bb1;
                }
                if (v1[mt]) {
                    int nn = nb + rn1[mt];
                    g_agg[((size_t)c0 * Nn + nn) * 9 + rs1[mt]] = acc[mt][2] + bb0;
                    g_agg[((size_t)c1 * Nn + nn) * 9 + rs1[mt]] = acc[mt][3] + bb1;
                }
            }
        } else {
            int eb = (blockIdx.x - NBN) * GN;
#pragma unroll
            for (int mt = 0; mt < 5; mt++) {
                if (v0[mt]) {
                    int ee = eb + rn0[mt];
                    g_eagg[((size_t)c0 * Ee + ee) * 9 + rs0[mt]] = acc[mt][0] + bb0;
                    g_eagg[((size_t)c1 * Ee + ee) * 9 + rs0[mt]] = acc[mt][1] + bb1;
                }
                if (v1[mt]) {
                    int ee = eb + rn1[mt];
                    g_eagg[((size_t)c0 * Ee + ee) * 9 + rs1[mt]] = acc[mt][2] + bb0;
                    g_eagg[((size_t)c1 * Ee + ee) * 9 + rs1[mt]] = acc[mt][3] + bb1;
                }
            }
        }
    }

    if (!isNode) return;

    // temporal conv + residual + relu (channels 61..63) — node blocks only
    for (int u = tid; u < GN * 36; u += 256) {
        int gg = u / 36, r = u % 36;
        int o3 = r / Tt, t = r % Tt;
        int nn = blockIdx.x * GN + gg;
        float xp = bt[61 + o3];
#pragma unroll
        for (int dk = 0; dk < 3; dk++) {
            int tau = t + dk - 1;
            if (tau >= 0 && tau < Tt) {
                const float* wt = swt + o3 * 192 + dk;
#pragma unroll 8
                for (int i = 0; i < 64; i++) xp = fmaf(wt[i * 3], sx[gg][i][tau], xp);
            }
        }
        float rs = br[61 + o3];
        const float* xr = nf + ((size_t)t * Nn + nn) * CINc;
#pragma unroll
        for (int cc = 0; cc < CINc; cc++) rs = fmaf(swr[o3 * 16 + cc], xr[cc], rs);
        shv[gg][o3][t] = fmaxf(xp + rs, 0.f);
    }
    __syncthreads();
    if (tid < GN * Pp) {
        int gg = tid / Pp, pc = tid % Pp;
        int nn = blockIdx.x * GN + gg;
        float a = bf[pc];
#pragma unroll
        for (int t = 0; t < Tt; t++)
#pragma unroll
            for (int dk = 0; dk < 3; dk++)
                a = fmaf(Wf[pc * 36 + t * 3 + dk], shv[gg][dk][t], a);
        out[(size_t)nn * Pp + pc] = a;
    }
}

// ---------------- score MLP: tf32 mma, 128 pairs x 64 h per block, 256 thr ----------------
__global__ void __launch_bounds__(256) k_mlp(
        const int* __restrict__ ni_full, const int* __restrict__ ei_full,
        const int* __restrict__ nni, const int* __restrict__ nei,
        const float* __restrict__ bm1,
        const float* __restrict__ Wm2, const float* __restrict__ bm2,
        float* __restrict__ out) {
    __shared__ unsigned zs[128][36];
    __shared__ unsigned ws[32][68];
    __shared__ int sn[128], se[128];
    __shared__ float sbm1[64], swm2[64];
    int tid = threadIdx.x;
    int q0 = blockIdx.x * 128;
    if (tid < 128) {
        int q = q0 + tid;
        int n, e;
        if (q < NNZn) { n = ni_full[11 * NNZn + q]; e = ei_full[11 * NNZn + q]; }
        else          { n = nni[q - NNZn];          e = nei[q - NNZn]; }
        sn[tid] = n; se[tid] = e;
    }
    if (tid < 64) { sbm1[tid] = bm1[tid]; swm2[tid] = Wm2[tid]; }
    __syncthreads();

    int w = tid >> 5;
    int lane = tid & 31;
    int g = lane >> 2, tg = lane & 3;
    int p0 = w * 16;

    float acc[8][4];
#pragma unroll
    for (int nt = 0; nt < 8; nt++)
#pragma unroll
        for (int j = 0; j < 4; j++) acc[nt][j] = 0.f;

    const float4* ag4 = (const float4*)g_agg;
    const float4* eg4 = (const float4*)g_eagg;
    int p = tid & 127, half = tid >> 7;
    int an = sn[p] * 144, ae = se[p] * 144;

    for (int c = 0; c < 18; c++) {
        __syncthreads();
        for (int j = tid; j < 512; j += 256) {
            uint4 t4 = g_wm1tf4[c * 512 + j];
            int k = j >> 4, h4 = j & 15;
            *(uint4*)&ws[k][h4 * 4] = t4;
        }
        {
            int base = an + c * 8 + half * 4;
            int ebase = ae + c * 8 + half * 4;
#pragma unroll
            for (int j = 0; j < 4; j++) {
                float4 a = ag4[base + j];
                float4 b = eg4[ebase + j];
                uint4 t4 = make_uint4(f2tf(a.x * b.x), f2tf(a.y * b.y),
                                      f2tf(a.z * b.z), f2tf(a.w * b.w));
                *(uint4*)&zs[p][half * 16 + j * 4] = t4;
            }
        }
        __syncthreads();
#pragma unroll
        for (int s = 0; s < 4; s++) {
            int kk = s * 8;
            unsigned a0 = zs[p0 + g][kk + tg];
            unsigned a1 = zs[p0 + g + 8][kk + tg];
            unsigned a2 = zs[p0 + g][kk + tg + 4];
            unsigned a3 = zs[p0 + g + 8][kk + tg + 4];
#pragma unroll
            for (int nt = 0; nt < 8; nt++) {
                unsigned b0 = ws[kk + tg][nt * 8 + g];
                unsigned b1 = ws[kk + tg + 4][nt * 8 + g];
                mma_tf32(acc[nt][0], acc[nt][1], acc[nt][2], acc[nt][3],
                         a0, a1, a2, a3, b0, b1);
            }
        }
    }

    float sum0 = 0.f, sum1 = 0.f;
#pragma unroll
    for (int nt = 0; nt < 8; nt++) {
        int h0 = nt * 8 + 2 * tg;
        float b0 = sbm1[h0], b1 = sbm1[h0 + 1];
        float w0 = swm2[h0], w1 = swm2[h0 + 1];
        sum0 += fmaxf(acc[nt][0] + b0, 0.f) * w0 + fmaxf(acc[nt][1] + b1, 0.f) * w1;
        sum1 += fmaxf(acc[nt][2] + b0, 0.f) * w0 + fmaxf(acc[nt][3] + b1, 0.f) * w1;
    }
    sum0 += __shfl_xor_sync(0xffffffffu, sum0, 1);
    sum0 += __shfl_xor_sync(0xffffffffu, sum0, 2);
    sum1 += __shfl_xor_sync(0xffffffffu, sum1, 1);
    sum1 += __shfl_xor_sync(0xffffffffu, sum1, 2);
    if (tg == 0) {
        float bb = bm2[0];
        out[(size_t)Nn * Pp + q0 + p0 + g] = sum0 + bb;
        out[(size_t)Nn * Pp + q0 + p0 + g + 8] = sum1 + bb;
    }
}

// ---------------- host launcher ----------------
extern "C" void kernel_launch(void* const* d_in, const int* in_sizes, int n_in,
                              void* d_out, int out_size) {
    const float* nf  = (const float*)d_in[0];
    const float* W1  = (const float*)d_in[1];
    const float* b1  = (const float*)d_in[2];
    const float* W2  = (const float*)d_in[3];
    const float* b2  = (const float*)d_in[4];
    const float* Wt  = (const float*)d_in[5];
    const float* bt  = (const float*)d_in[6];
    const float* Wr  = (const float*)d_in[7];
    const float* br  = (const float*)d_in[8];
    const float* Wf  = (const float*)d_in[9];
    const float* bf  = (const float*)d_in[10];
    const float* Wna = (const float*)d_in[11];
    const float* bna = (const float*)d_in[12];
    const float* Wea = (const float*)d_in[13];
    const float* bea = (const float*)d_in[14];
    const float* Wm1 = (const float*)d_in[15];
    const float* bm1 = (const float*)d_in[16];
    const float* Wm2 = (const float*)d_in[17];
    const float* bm2 = (const float*)d_in[18];
    const int* node_idx = (const int*)d_in[19];
    const int* edge_idx = (const int*)d_in[20];
    const int* nni = (const int*)d_in[21];
    const int* nei = (const int*)d_in[22];
    float* out = (float*)d_out;

    int nbE = (TE + 4095) / 4096;
    int nbN = (TN + 4095) / 4096;

    k_zero<<<2048, 256>>>();
    k_count<<<(TNNZ + 255) / 256, 256>>>(node_idx, edge_idx);
    k_inv<<<(TN + 255) / 256, 256>>>();
    k_scanA<0><<<nbE, 256>>>();
    k_scanB<<<1, 1024>>>(nbE);
    k_scanC<0><<<nbE, 256>>>();
    k_scanA<1><<<nbN, 256>>>();
    k_scanB<<<1, 1024>>>(nbN);
    k_scanC<1><<<nbN, 256>>>();
    k_fill<<<(TNNZ + 255) / 256, 256>>>(node_idx, edge_idx);
    k_prep<<<(576 * 64 + 255) / 256, 256>>>(Wna, Wea, Wm1);

    k_e1<<<TE / 16, 256>>>(nf, W1, b1);
    k_es2<<<TE / 16, 256>>>(W2, b2);

    k_heads<<<NBN + NBE, 256>>>(nf, bna, bea, Wt, bt, Wr, br, Wf, bf, out);
    k_mlp<<<(2 * NNZn) / 128, 256>>>(node_idx, edge_idx, nni, nei, bm1, Wm2, bm2, out);
}